// round 7
// baseline (speedup 1.0000x reference)
#include <cuda_runtime.h>
#include <cuda_bf16.h>

// ---------------------------------------------------------------------------
// GCN: out = relu(Â X W1 + b1) -> relu(Â H W2 + b2) -> @Wfc + bfc
// Â = D^-1/2 (A+I) D^-1/2.  Aggregate-first + CSR gather, no global atomics.
// Edge dtype detected on-device (JAX downcasts int64->int32 without x64).
//   p[u]  = d[u]*in[u]
//   agg[v]= p[v] + sum_{(u->v)} p[u]      <-- self UNscaled (GEMM row-scale
//   conv[v] = relu( (d[v]*agg[v]) @ W+b )     supplies the second d[v])
// ---------------------------------------------------------------------------

#define NMAX   50176
#define EMAX   1048576
#define F1     128
#define H      256
#define SCAN_B 1024
#define NPB    1024      // nodes per block in histogram/fill kernels

__device__ int   g_is64;
__device__ int   g_src   [EMAX];
__device__ int   g_dst   [EMAX];
__device__ int   g_cnt   [NMAX];       // in-degree (excl. self loop)
__device__ int   g_rowptr[NMAX];       // CSR row starts (end = start + cnt)
__device__ int   g_eidx  [EMAX];       // CSR column (src node) ids
__device__ int   g_bsum  [64];         // scan block sums
__device__ int   g_boff  [64];         // scan block offsets
__device__ float g_dinv  [NMAX];
__device__ float g_p1  [(size_t)NMAX * F1];   // d[u]*x[u]
__device__ float g_agg1[(size_t)NMAX * F1];
__device__ float g_p2  [(size_t)NMAX * H];    // d[u]*h1[u]
__device__ float g_agg2[(size_t)NMAX * H];
__device__ float g_part[(size_t)NMAX * 2];    // final-dot partials (2 col halves)

// --------------------------- edge ingest -----------------------------------

// int64 layout <=> every odd 32-bit word of the first 1024 entries is zero
// (indices < n < 2^31). For int32 data those words are random edge ids.
__global__ void k_detect(const int* __restrict__ w) {
    __shared__ int any;
    if (threadIdx.x == 0) any = 0;
    __syncthreads();
    for (int i = threadIdx.x; i < 1024; i += blockDim.x)
        if (w[2 * i + 1] != 0) any = 1;
    __syncthreads();
    if (threadIdx.x == 0) g_is64 = (any == 0);
}

// Decode edge_index[2][E] into clean int arrays, clamped to [0, n).
__global__ void k_extract(const void* __restrict__ ei, int E, int n) {
    int i = blockIdx.x * blockDim.x + threadIdx.x;
    if (i >= 2 * E) return;
    long long v = g_is64 ? ((const long long*)ei)[i]
                         : (long long)((const int*)ei)[i];
    int c = (int)v;
    c = (c < 0) ? 0 : ((c >= n) ? n - 1 : c);
    if (i < E) g_src[i] = c;
    else       g_dst[i - E] = c;
}

// --------------------------- CSR build (no global atomics) ------------------

// Block b owns nodes [b*NPB, b*NPB+NPB); scans ALL edges, histograms into smem.
__global__ void k_count_range(int E, int n) {
    __shared__ int hist[NPB];
    int base = blockIdx.x * NPB;
    hist[threadIdx.x] = 0;
    __syncthreads();
    for (int e = threadIdx.x; e < E; e += NPB) {
        unsigned d = (unsigned)(g_dst[e] - base);
        if (d < NPB) atomicAdd(&hist[d], 1);          // shared-memory atomic
    }
    __syncthreads();
    int node = base + threadIdx.x;
    if (node < n) g_cnt[node] = hist[threadIdx.x];
}

__global__ void k_scan_block(int n) {
    __shared__ int s[SCAN_B];
    int t = threadIdx.x;
    int i = blockIdx.x * SCAN_B + t;
    int v = (i < n) ? g_cnt[i] : 0;
    s[t] = v;
    __syncthreads();
#pragma unroll
    for (int off = 1; off < SCAN_B; off <<= 1) {
        int x = (t >= off) ? s[t - off] : 0;
        __syncthreads();
        s[t] += x;
        __syncthreads();
    }
    if (i < n) g_rowptr[i] = s[t] - v;             // exclusive, pre-offset
    if (t == SCAN_B - 1) g_bsum[blockIdx.x] = s[t];
}

__global__ void k_scan_sums(int nb) {
    __shared__ int s[64];
    int t = threadIdx.x;
    int v = (t < nb) ? g_bsum[t] : 0;
    s[t] = v;
    __syncthreads();
#pragma unroll
    for (int off = 1; off < 64; off <<= 1) {
        int x = (t >= off) ? s[t - off] : 0;
        __syncthreads();
        s[t] += x;
        __syncthreads();
    }
    if (t < nb) g_boff[t] = s[t] - v;              // exclusive
}

__global__ void k_scan_add(int n) {
    int i = blockIdx.x * blockDim.x + threadIdx.x;
    if (i < n) g_rowptr[i] += g_boff[i / SCAN_B];
}

// Block b owns nodes [b*NPB, ...); scans all edges, places srcs via smem cursors.
__global__ void k_fill_range(int E, int n) {
    __shared__ int cur[NPB];
    int base = blockIdx.x * NPB;
    int node = base + threadIdx.x;
    cur[threadIdx.x] = (node < n) ? g_rowptr[node] : 0;
    __syncthreads();
    for (int e = threadIdx.x; e < E; e += NPB) {
        unsigned d = (unsigned)(g_dst[e] - base);
        if (d < NPB) {
            int pos = atomicAdd(&cur[d], 1);          // shared-memory atomic
            g_eidx[pos] = g_src[e];
        }
    }
}

// --------------------------- node prep -------------------------------------

// dinv = rsqrt(deg), deg = cnt+1 (self loop); p1 = d*x. One warp per node.
__global__ void k_prep(const float* __restrict__ x, int n) {
    int w = (blockIdx.x * blockDim.x + threadIdx.x) >> 5;
    if (w >= n) return;
    int lane = threadIdx.x & 31;
    float d = rsqrtf((float)(g_cnt[w] + 1));
    if (lane == 0) g_dinv[w] = d;
    float4 v = ((const float4*)(x + (size_t)w * F1))[lane];
    ((float4*)(g_p1 + (size_t)w * F1))[lane] =
        make_float4(v.x * d, v.y * d, v.z * d, v.w * d);
}

// --------------------------- gather aggregation -----------------------------

// agg[v] = p[v] + sum p[u]   (self term UNscaled; GEMM row-scale adds d[v])
__global__ void k_agg1(int n) {
    int v = (blockIdx.x * blockDim.x + threadIdx.x) >> 5;
    if (v >= n) return;
    int lane = threadIdx.x & 31;
    float4 acc = ((const float4*)(g_p1 + (size_t)v * F1))[lane];
    int start = g_rowptr[v], end = start + g_cnt[v];
    for (int i = start; i < end; i++) {
        int u = g_eidx[i];
        float4 m = ((const float4*)(g_p1 + (size_t)u * F1))[lane];
        acc.x += m.x; acc.y += m.y; acc.z += m.z; acc.w += m.w;
    }
    ((float4*)(g_agg1 + (size_t)v * F1))[lane] = acc;
}

__global__ void k_agg2(int n) {
    int v = (blockIdx.x * blockDim.x + threadIdx.x) >> 5;
    if (v >= n) return;
    int lane = threadIdx.x & 31;
    const float4* pr = (const float4*)(g_p2 + (size_t)v * H);
    float4 a0 = pr[lane];
    float4 a1 = pr[lane + 32];
    int start = g_rowptr[v], end = start + g_cnt[v];
    for (int i = start; i < end; i++) {
        int u = g_eidx[i];
        const float4* mr = (const float4*)(g_p2 + (size_t)u * H);
        float4 m0 = mr[lane], m1 = mr[lane + 32];
        a0.x += m0.x; a0.y += m0.y; a0.z += m0.z; a0.w += m0.w;
        a1.x += m1.x; a1.y += m1.y; a1.z += m1.z; a1.w += m1.w;
    }
    float4* ar = (float4*)(g_agg2 + (size_t)v * H);
    ar[lane] = a0;
    ar[lane + 32] = a1;
}

// ---------------------------------------------------------------------------
// SIMT fp32 GEMM: C = (diag(dinv) * A) @ W, 128x128 tile, BK=8, 2x2x(4x4) frag
// EPI==1: p2 = d*relu(C+b1)                               (A = g_agg1, K=128)
// EPI==2: g_part[r][colHalf] = sum_c relu(C+b2)*Wfc[c]    (A = g_agg2, K=256)
// ---------------------------------------------------------------------------
template <int K, int EPI>
__global__ void __launch_bounds__(256, 2)
k_gemm(const float* __restrict__ W, const float* __restrict__ bias,
       const float* __restrict__ Wfc, int M) {
    const int NC = H;
    const float* __restrict__ A = (EPI == 1) ? g_agg1 : g_agg2;

    __shared__ float As[8][128];
    __shared__ float Bs[8][128];

    int tid = threadIdx.x;
    int tx = tid & 15, ty = tid >> 4;
    int rowBase = blockIdx.y * 128, colBase = blockIdx.x * 128;

    int aRow = tid >> 1;
    int aCol = (tid & 1) * 4;
    int bRow = tid >> 5;
    int bCol = (tid & 31) * 4;

    bool aValid = (rowBase + aRow) < M;
    float dA = aValid ? g_dinv[rowBase + aRow] : 0.0f;

    float acc[2][2][4][4];
#pragma unroll
    for (int a = 0; a < 2; a++)
#pragma unroll
        for (int b = 0; b < 2; b++)
#pragma unroll
            for (int i = 0; i < 4; i++)
#pragma unroll
                for (int j = 0; j < 4; j++) acc[a][b][i][j] = 0.0f;

    for (int k0 = 0; k0 < K; k0 += 8) {
        float4 av = make_float4(0.f, 0.f, 0.f, 0.f);
        if (aValid)
            av = *(const float4*)(A + (size_t)(rowBase + aRow) * K + k0 + aCol);
        As[aCol + 0][aRow] = av.x * dA;
        As[aCol + 1][aRow] = av.y * dA;
        As[aCol + 2][aRow] = av.z * dA;
        As[aCol + 3][aRow] = av.w * dA;
        *(float4*)&Bs[bRow][bCol] =
            *(const float4*)(W + (size_t)(k0 + bRow) * NC + colBase + bCol);
        __syncthreads();
#pragma unroll
        for (int kk = 0; kk < 8; kk++) {
            float4 a0 = *(float4*)&As[kk][ty * 4];
            float4 a1 = *(float4*)&As[kk][64 + ty * 4];
            float4 b0 = *(float4*)&Bs[kk][tx * 4];
            float4 b1 = *(float4*)&Bs[kk][64 + tx * 4];
            float ar[2][4] = {{a0.x, a0.y, a0.z, a0.w}, {a1.x, a1.y, a1.z, a1.w}};
            float br[2][4] = {{b0.x, b0.y, b0.z, b0.w}, {b1.x, b1.y, b1.z, b1.w}};
#pragma unroll
            for (int ri = 0; ri < 2; ri++)
#pragma unroll
                for (int ci = 0; ci < 2; ci++)
#pragma unroll
                    for (int i = 0; i < 4; i++)
#pragma unroll
                        for (int j = 0; j < 4; j++)
                            acc[ri][ci][i][j] += ar[ri][i] * br[ci][j];
        }
        __syncthreads();
    }

    if (EPI == 1) {
#pragma unroll
        for (int ri = 0; ri < 2; ri++)
#pragma unroll
            for (int i = 0; i < 4; i++) {
                int r = rowBase + ri * 64 + ty * 4 + i;
                if (r >= M) continue;
                float d = g_dinv[r];
#pragma unroll
                for (int ci = 0; ci < 2; ci++)
#pragma unroll
                    for (int j = 0; j < 4; j++) {
                        int c = colBase + ci * 64 + tx * 4 + j;
                        float h = fmaxf(acc[ri][ci][i][j] + bias[c], 0.0f);
                        g_p2[(size_t)r * NC + c] = d * h;
                    }
            }
    } else {
        // per-thread partial dot over its 8 columns, reduce across tx in smem
        __shared__ float sred[128][17];
#pragma unroll
        for (int ri = 0; ri < 2; ri++)
#pragma unroll
            for (int i = 0; i < 4; i++) {
                float partial = 0.0f;
#pragma unroll
                for (int ci = 0; ci < 2; ci++)
#pragma unroll
                    for (int j = 0; j < 4; j++) {
                        int c = colBase + ci * 64 + tx * 4 + j;
                        float h = fmaxf(acc[ri][ci][i][j] + bias[c], 0.0f);
                        partial += h * Wfc[c];
                    }
                sred[ri * 64 + ty * 4 + i][tx] = partial;
            }
        __syncthreads();
        if (tid < 128) {
            float s = 0.0f;
#pragma unroll
            for (int k = 0; k < 16; k++) s += sred[tid][k];
            int r = rowBase + tid;
            if (r < M) g_part[(size_t)r * 2 + blockIdx.x] = s;
        }
    }
}

__global__ void k_final(const float* __restrict__ bfc, float* __restrict__ out, int n) {
    int i = blockIdx.x * blockDim.x + threadIdx.x;
    if (i < n) out[i] = g_part[(size_t)i * 2] + g_part[(size_t)i * 2 + 1] + bfc[0];
}

// ---------------------------------------------------------------------------

extern "C" void kernel_launch(void* const* d_in, const int* in_sizes, int n_in,
                              void* d_out, int out_size) {
    const float* x   = (const float*)d_in[0];
    const void*  ei  = d_in[1];
    const float* W1  = (const float*)d_in[2];
    const float* b1  = (const float*)d_in[3];
    const float* W2  = (const float*)d_in[4];
    const float* b2  = (const float*)d_in[5];
    const float* Wfc = (const float*)d_in[6];
    const float* bfc = (const float*)d_in[7];
    float*       out = (float*)d_out;

    int h   = in_sizes[3];            // 256
    int fin = in_sizes[2] / h;        // 128
    int n   = in_sizes[0] / fin;      // 50000
    int E   = in_sizes[1] / 2;        // 800000
    (void)h; (void)n_in; (void)out_size;

    int nb  = (n + SCAN_B - 1) / SCAN_B;          // 49
    int nbh = (n + NPB - 1) / NPB;                // 49

    k_detect <<<1, 256>>>((const int*)ei);
    k_extract<<<(2 * E + 255) / 256, 256>>>(ei, E, n);

    k_count_range<<<nbh, NPB>>>(E, n);
    k_scan_block<<<nb, SCAN_B>>>(n);
    k_scan_sums<<<1, 64>>>(nb);
    k_scan_add<<<(n + 255) / 256, 256>>>(n);
    k_fill_range<<<nbh, NPB>>>(E, n);

    k_prep<<<(n * 32 + 255) / 256, 256>>>(x, n);
    k_agg1<<<(n * 32 + 255) / 256, 256>>>(n);

    dim3 gg(2, (n + 127) / 128);
    k_gemm<F1, 1><<<gg, 256>>>(W1, b1, nullptr, n);
    k_agg2<<<(n * 32 + 255) / 256, 256>>>(n);
    k_gemm<H, 2><<<gg, 256>>>(W2, b2, Wfc, n);
    k_final<<<(n + 255) / 256, 256>>>(bfc, out, n);
}

// round 8
// speedup vs baseline: 2.0136x; 2.0136x over previous
#include <cuda_runtime.h>
#include <cuda_bf16.h>
#include <cstdint>

// ---------------------------------------------------------------------------
// GCN: out = relu(Â X W1 + b1) -> relu(Â H W2 + b2) -> @Wfc + bfc
// Â = D^-1/2 (A+I) D^-1/2.  Aggregate-first + CSR gather (global int atomics),
// tensor-core GEMM (mma.sync bf16, 3-term hi/lo split for ~fp32 accuracy).
//   p[u]  = d[u]*in[u];  agg[v] = p[v] + sum_{(u->v)} p[u]
//   conv[v] = relu( (d[v]*agg[v]) @ W + b )
// ---------------------------------------------------------------------------

#define NMAX   50176
#define EMAX   1048576
#define F1     128
#define H      256
#define SCAN_B 1024

__device__ int   g_is64;
__device__ int   g_src   [EMAX];
__device__ int   g_dst   [EMAX];
__device__ int   g_cnt   [NMAX];
__device__ int   g_fill  [NMAX];
__device__ int   g_rowptr[NMAX];
__device__ int   g_eidx  [EMAX];
__device__ int   g_bsum  [64];
__device__ int   g_boff  [64];
__device__ float g_dinv  [NMAX];
__device__ float g_p1  [(size_t)NMAX * F1];
__device__ float g_agg1[(size_t)NMAX * F1];
__device__ float g_p2  [(size_t)NMAX * H];
__device__ float g_agg2[(size_t)NMAX * H];
__device__ float g_part[(size_t)NMAX * 4];   // final-dot partials (2 blocks x 2 warpN)

// --------------------------- edge ingest -----------------------------------

__global__ void k_detect(const int* __restrict__ w) {
    __shared__ int any;
    if (threadIdx.x == 0) any = 0;
    __syncthreads();
    for (int i = threadIdx.x; i < 1024; i += blockDim.x)
        if (w[2 * i + 1] != 0) any = 1;
    __syncthreads();
    if (threadIdx.x == 0) g_is64 = (any == 0);
}

__global__ void k_extract(const void* __restrict__ ei, int E, int n) {
    int i = blockIdx.x * blockDim.x + threadIdx.x;
    if (i >= 2 * E) return;
    long long v = g_is64 ? ((const long long*)ei)[i]
                         : (long long)((const int*)ei)[i];
    int c = (int)v;
    c = (c < 0) ? 0 : ((c >= n) ? n - 1 : c);
    if (i < E) g_src[i] = c;
    else       g_dst[i - E] = c;
}

// --------------------------- CSR build (global int atomics) -----------------

__global__ void k_initcnt(int n) {
    int i = blockIdx.x * blockDim.x + threadIdx.x;
    if (i < n) { g_cnt[i] = 0; g_fill[i] = 0; }
}

__global__ void k_count(int E) {
    int e = blockIdx.x * blockDim.x + threadIdx.x;
    if (e < E) atomicAdd(&g_cnt[g_dst[e]], 1);
}

__global__ void k_scan_block(int n) {
    __shared__ int s[SCAN_B];
    int t = threadIdx.x;
    int i = blockIdx.x * SCAN_B + t;
    int v = (i < n) ? g_cnt[i] : 0;
    s[t] = v;
    __syncthreads();
#pragma unroll
    for (int off = 1; off < SCAN_B; off <<= 1) {
        int x = (t >= off) ? s[t - off] : 0;
        __syncthreads();
        s[t] += x;
        __syncthreads();
    }
    if (i < n) g_rowptr[i] = s[t] - v;
    if (t == SCAN_B - 1) g_bsum[blockIdx.x] = s[t];
}

__global__ void k_scan_sums(int nb) {
    __shared__ int s[64];
    int t = threadIdx.x;
    int v = (t < nb) ? g_bsum[t] : 0;
    s[t] = v;
    __syncthreads();
#pragma unroll
    for (int off = 1; off < 64; off <<= 1) {
        int x = (t >= off) ? s[t - off] : 0;
        __syncthreads();
        s[t] += x;
        __syncthreads();
    }
    if (t < nb) g_boff[t] = s[t] - v;
}

__global__ void k_scan_add(int n) {
    int i = blockIdx.x * blockDim.x + threadIdx.x;
    if (i < n) g_rowptr[i] += g_boff[i / SCAN_B];
}

__global__ void k_fill(int E) {
    int e = blockIdx.x * blockDim.x + threadIdx.x;
    if (e >= E) return;
    int d = g_dst[e];
    int pos = g_rowptr[d] + atomicAdd(&g_fill[d], 1);
    g_eidx[pos] = g_src[e];
}

// --------------------------- node prep -------------------------------------

__global__ void k_prep(const float* __restrict__ x, int n) {
    int w = (blockIdx.x * blockDim.x + threadIdx.x) >> 5;
    if (w >= n) return;
    int lane = threadIdx.x & 31;
    float d = rsqrtf((float)(g_cnt[w] + 1));
    if (lane == 0) g_dinv[w] = d;
    float4 v = ((const float4*)(x + (size_t)w * F1))[lane];
    ((float4*)(g_p1 + (size_t)w * F1))[lane] =
        make_float4(v.x * d, v.y * d, v.z * d, v.w * d);
}

// --------------------------- gather aggregation -----------------------------

__global__ void k_agg1(int n) {
    int v = (blockIdx.x * blockDim.x + threadIdx.x) >> 5;
    if (v >= n) return;
    int lane = threadIdx.x & 31;
    float4 acc = ((const float4*)(g_p1 + (size_t)v * F1))[lane];
    int start = g_rowptr[v], end = start + g_cnt[v];
    for (int i = start; i < end; i++) {
        int u = g_eidx[i];
        float4 m = ((const float4*)(g_p1 + (size_t)u * F1))[lane];
        acc.x += m.x; acc.y += m.y; acc.z += m.z; acc.w += m.w;
    }
    ((float4*)(g_agg1 + (size_t)v * F1))[lane] = acc;
}

__global__ void k_agg2(int n) {
    int v = (blockIdx.x * blockDim.x + threadIdx.x) >> 5;
    if (v >= n) return;
    int lane = threadIdx.x & 31;
    const float4* pr = (const float4*)(g_p2 + (size_t)v * H);
    float4 a0 = pr[lane];
    float4 a1 = pr[lane + 32];
    int start = g_rowptr[v], end = start + g_cnt[v];
    for (int i = start; i < end; i++) {
        int u = g_eidx[i];
        const float4* mr = (const float4*)(g_p2 + (size_t)u * H);
        float4 m0 = mr[lane], m1 = mr[lane + 32];
        a0.x += m0.x; a0.y += m0.y; a0.z += m0.z; a0.w += m0.w;
        a1.x += m1.x; a1.y += m1.y; a1.z += m1.z; a1.w += m1.w;
    }
    float4* ar = (float4*)(g_agg2 + (size_t)v * H);
    ar[lane] = a0;
    ar[lane + 32] = a1;
}

// ---------------------------------------------------------------------------
// Tensor-core GEMM: C = (diag(dinv)*A) @ W via mma.sync m16n8k16 bf16,
// 3-term split (ah*bh + ah*bl + al*bh) for ~1e-5 relative accuracy.
// Block tile 128x128, BK=32, 8 warps (4M x 2N), warp tile 32x64.
// Smem [row][40 bf16] (20-word stride): frag loads bank-conflict-free.
// EPI==1: p2 = d*relu(C+b1)                        (A=g_agg1, K=128)
// EPI==2: g_part[r][2*bx+warpN] = relu(C+b2)@Wfc   (A=g_agg2, K=256)
// ---------------------------------------------------------------------------

__device__ __forceinline__ void split_bf16(float x, __nv_bfloat16& h, __nv_bfloat16& l) {
    h = __float2bfloat16_rn(x);
    l = __float2bfloat16_rn(x - __bfloat162float(h));
}

__device__ __forceinline__ void mma_bf16(float* c, const uint32_t* a,
                                         uint32_t b0, uint32_t b1) {
    asm volatile(
        "mma.sync.aligned.m16n8k16.row.col.f32.bf16.bf16.f32 "
        "{%0,%1,%2,%3}, {%4,%5,%6,%7}, {%8,%9}, {%0,%1,%2,%3};\n"
        : "+f"(c[0]), "+f"(c[1]), "+f"(c[2]), "+f"(c[3])
        : "r"(a[0]), "r"(a[1]), "r"(a[2]), "r"(a[3]), "r"(b0), "r"(b1));
}

template <int K, int EPI>
__global__ void __launch_bounds__(256)
k_gemm_tc(const float* __restrict__ W, const float* __restrict__ bias,
          const float* __restrict__ Wfc, int M) {
    const int NC = H;
    const float* __restrict__ A = (EPI == 1) ? g_agg1 : g_agg2;

    __shared__ __align__(16) __nv_bfloat16 sAh[128 * 40];
    __shared__ __align__(16) __nv_bfloat16 sAl[128 * 40];
    __shared__ __align__(16) __nv_bfloat16 sBh[128 * 40];   // [n][k] = W^T tile
    __shared__ __align__(16) __nv_bfloat16 sBl[128 * 40];

    int tid = threadIdx.x, lane = tid & 31, warp = tid >> 5;
    int warpM = warp & 3, warpN = warp >> 2;
    int rowBase = blockIdx.y * 128, colBase = blockIdx.x * 128;

    float acc[2][8][4];
#pragma unroll
    for (int mf = 0; mf < 2; mf++)
#pragma unroll
        for (int nf = 0; nf < 8; nf++)
#pragma unroll
            for (int i = 0; i < 4; i++) acc[mf][nf][i] = 0.0f;

    // per-thread A-load coordinates (fixed across k tiles)
    int aRowL[4]; float aD[4]; bool aV[4];
#pragma unroll
    for (int i = 0; i < 4; i++) {
        int fid = tid + i * 256;
        aRowL[i] = fid >> 3;                        // 0..127
        int r = rowBase + aRowL[i];
        aV[i] = r < M;
        aD[i] = aV[i] ? g_dinv[r] : 0.0f;
    }
    int nB = tid & 127, kg = tid >> 7;              // B fill coords

    for (int k0 = 0; k0 < K; k0 += 32) {
        // ---- A tile: 128 x 32 fp32 -> split bf16, [m][40] layout
#pragma unroll
        for (int i = 0; i < 4; i++) {
            int fid = tid + i * 256;
            int row = aRowL[i], kq = fid & 7;
            float4 av = make_float4(0.f, 0.f, 0.f, 0.f);
            if (aV[i]) {
                av = *(const float4*)(A + (size_t)(rowBase + row) * K + k0 + kq * 4);
                av.x *= aD[i]; av.y *= aD[i]; av.z *= aD[i]; av.w *= aD[i];
            }
            __nv_bfloat16 h0, l0, h1, l1, h2, l2, h3, l3;
            split_bf16(av.x, h0, l0); split_bf16(av.y, h1, l1);
            split_bf16(av.z, h2, l2); split_bf16(av.w, h3, l3);
            int base = row * 40 + kq * 4;
            *(__nv_bfloat162*)&sAh[base]     = __halves2bfloat162(h0, h1);
            *(__nv_bfloat162*)&sAh[base + 2] = __halves2bfloat162(h2, h3);
            *(__nv_bfloat162*)&sAl[base]     = __halves2bfloat162(l0, l1);
            *(__nv_bfloat162*)&sAl[base + 2] = __halves2bfloat162(l2, l3);
        }
        // ---- B tile: W[k0..k0+32) x 128 cols -> transposed [n][40]
        {
            const float* Wp = W + (size_t)(k0 + kg * 16) * NC + colBase + nB;
#pragma unroll
            for (int i = 0; i < 16; i++) {
                __nv_bfloat16 h, l;
                split_bf16(Wp[(size_t)i * NC], h, l);
                sBh[nB * 40 + kg * 16 + i] = h;
                sBl[nB * 40 + kg * 16 + i] = l;
            }
        }
        __syncthreads();

        const uint32_t* pAh = (const uint32_t*)sAh;
        const uint32_t* pAl = (const uint32_t*)sAl;
        const uint32_t* pBh = (const uint32_t*)sBh;
        const uint32_t* pBl = (const uint32_t*)sBl;

#pragma unroll
        for (int ks = 0; ks < 32; ks += 16) {
            int kw = (ks >> 1) + (lane & 3);
            uint32_t ah[2][4], al[2][4];
#pragma unroll
            for (int mf = 0; mf < 2; mf++) {
                int r0 = (warpM * 32 + mf * 16 + (lane >> 2)) * 20;
                int r1 = r0 + 8 * 20;
                ah[mf][0] = pAh[r0 + kw];     ah[mf][1] = pAh[r1 + kw];
                ah[mf][2] = pAh[r0 + kw + 4]; ah[mf][3] = pAh[r1 + kw + 4];
                al[mf][0] = pAl[r0 + kw];     al[mf][1] = pAl[r1 + kw];
                al[mf][2] = pAl[r0 + kw + 4]; al[mf][3] = pAl[r1 + kw + 4];
            }
#pragma unroll
            for (int nf = 0; nf < 8; nf++) {
                int nr = (warpN * 64 + nf * 8 + (lane >> 2)) * 20;
                uint32_t b0h = pBh[nr + kw], b1h = pBh[nr + kw + 4];
                uint32_t b0l = pBl[nr + kw], b1l = pBl[nr + kw + 4];
#pragma unroll
                for (int mf = 0; mf < 2; mf++) {
                    mma_bf16(acc[mf][nf], ah[mf], b0h, b1h);
                    mma_bf16(acc[mf][nf], ah[mf], b0l, b1l);
                    mma_bf16(acc[mf][nf], al[mf], b0h, b1h);
                }
            }
        }
        __syncthreads();
    }

    // ---- epilogue
    if (EPI == 1) {
#pragma unroll
        for (int mf = 0; mf < 2; mf++)
#pragma unroll
            for (int rr = 0; rr < 2; rr++) {
                int r = rowBase + warpM * 32 + mf * 16 + (lane >> 2) + rr * 8;
                if (r >= M) continue;
                float d = g_dinv[r];
#pragma unroll
                for (int nf = 0; nf < 8; nf++) {
                    int c = colBase + warpN * 64 + nf * 8 + (lane & 3) * 2;
                    float v0 = fmaxf(acc[mf][nf][rr * 2 + 0] + bias[c], 0.f) * d;
                    float v1 = fmaxf(acc[mf][nf][rr * 2 + 1] + bias[c + 1], 0.f) * d;
                    float2 vv = make_float2(v0, v1);
                    *(float2*)&g_p2[(size_t)r * NC + c] = vv;
                }
            }
    } else {
#pragma unroll
        for (int mf = 0; mf < 2; mf++)
#pragma unroll
            for (int rr = 0; rr < 2; rr++) {
                float p = 0.0f;
#pragma unroll
                for (int nf = 0; nf < 8; nf++) {
                    int c = colBase + warpN * 64 + nf * 8 + (lane & 3) * 2;
                    p += fmaxf(acc[mf][nf][rr * 2 + 0] + bias[c], 0.f) * Wfc[c];
                    p += fmaxf(acc[mf][nf][rr * 2 + 1] + bias[c + 1], 0.f) * Wfc[c + 1];
                }
                p += __shfl_xor_sync(0xFFFFFFFFu, p, 1);
                p += __shfl_xor_sync(0xFFFFFFFFu, p, 2);
                int r = rowBase + warpM * 32 + mf * 16 + (lane >> 2) + rr * 8;
                if ((lane & 3) == 0 && r < M)
                    g_part[(size_t)r * 4 + blockIdx.x * 2 + warpN] = p;
            }
    }
}

__global__ void k_final(const float* __restrict__ bfc, float* __restrict__ out, int n) {
    int i = blockIdx.x * blockDim.x + threadIdx.x;
    if (i < n)
        out[i] = g_part[(size_t)i * 4] + g_part[(size_t)i * 4 + 1]
               + g_part[(size_t)i * 4 + 2] + g_part[(size_t)i * 4 + 3] + bfc[0];
}

// ---------------------------------------------------------------------------

extern "C" void kernel_launch(void* const* d_in, const int* in_sizes, int n_in,
                              void* d_out, int out_size) {
    const float* x   = (const float*)d_in[0];
    const void*  ei  = d_in[1];
    const float* W1  = (const float*)d_in[2];
    const float* b1  = (const float*)d_in[3];
    const float* W2  = (const float*)d_in[4];
    const float* b2  = (const float*)d_in[5];
    const float* Wfc = (const float*)d_in[6];
    const float* bfc = (const float*)d_in[7];
    float*       out = (float*)d_out;

    int h   = in_sizes[3];            // 256
    int fin = in_sizes[2] / h;        // 128
    int n   = in_sizes[0] / fin;      // 50000
    int E   = in_sizes[1] / 2;        // 800000
    (void)h; (void)n_in; (void)out_size;

    int nb = (n + SCAN_B - 1) / SCAN_B;           // 49

    k_detect <<<1, 256>>>((const int*)ei);
    k_extract<<<(2 * E + 255) / 256, 256>>>(ei, E, n);

    k_initcnt<<<(n + 255) / 256, 256>>>(n);
    k_count  <<<(E + 255) / 256, 256>>>(E);
    k_scan_block<<<nb, SCAN_B>>>(n);
    k_scan_sums<<<1, 64>>>(nb);
    k_scan_add<<<(n + 255) / 256, 256>>>(n);
    k_fill   <<<(E + 255) / 256, 256>>>(E);

    k_prep<<<(n * 32 + 255) / 256, 256>>>(x, n);
    k_agg1<<<(n * 32 + 255) / 256, 256>>>(n);

    dim3 gg(2, (n + 127) / 128);
    k_gemm_tc<F1, 1><<<gg, 256>>>(W1, b1, nullptr, n);
    k_agg2<<<(n * 32 + 255) / 256, 256>>>(n);
    k_gemm_tc<H, 2><<<gg, 256>>>(W2, b2, Wfc, n);
    k_final<<<(n + 255) / 256, 256>>>(bfc, out, n);
}

// round 10
// speedup vs baseline: 2.1788x; 1.0820x over previous
#include <cuda_runtime.h>
#include <cuda_bf16.h>
#include <cstdint>

// ---------------------------------------------------------------------------
// GCN: out = relu(Â X W1 + b1) -> relu(Â H W2 + b2) -> @Wfc + bfc
// Aggregate-first + CSR gather; GEMM operands pre-split to bf16 hi/lo
// (3-term mma.sync emulation ~1e-5 accuracy); cp.async double-buffered GEMM.
// ---------------------------------------------------------------------------

#define NMAX   50176
#define EMAX   1048576
#define F1     128
#define H      256
#define SCAN_B 1024

__device__ int   g_is64;
__device__ int   g_src   [EMAX];
__device__ int   g_dst   [EMAX];
__device__ int   g_cnt   [NMAX];
__device__ int   g_fill  [NMAX];
__device__ int   g_rowptr[NMAX];
__device__ int   g_eidx  [EMAX];
__device__ int   g_bsum  [64];
__device__ int   g_boff  [64];
__device__ float g_dinv  [NMAX];
__device__ float g_p1  [(size_t)NMAX * F1];     // d[u]*x[u]
__device__ float g_p2  [(size_t)NMAX * H];      // d[u]*h1[u]
__device__ float g_part[(size_t)NMAX * 4];

// pre-split bf16 operands (16B aligned for cp.async)
__device__ __align__(16) __nv_bfloat16 g_a1h[(size_t)NMAX * F1];
__device__ __align__(16) __nv_bfloat16 g_a1l[(size_t)NMAX * F1];
__device__ __align__(16) __nv_bfloat16 g_a2h[(size_t)NMAX * H];
__device__ __align__(16) __nv_bfloat16 g_a2l[(size_t)NMAX * H];
__device__ __align__(16) __nv_bfloat16 g_w1h[(size_t)H * F1];   // [n][k] transposed
__device__ __align__(16) __nv_bfloat16 g_w1l[(size_t)H * F1];
__device__ __align__(16) __nv_bfloat16 g_w2h[(size_t)H * H];
__device__ __align__(16) __nv_bfloat16 g_w2l[(size_t)H * H];

__device__ __forceinline__ void split_bf16(float x, __nv_bfloat16& h, __nv_bfloat16& l) {
    h = __float2bfloat16_rn(x);
    l = __float2bfloat16_rn(x - __bfloat162float(h));
}

// --------------------------- edge ingest -----------------------------------

__global__ void k_detect(const int* __restrict__ w) {
    __shared__ int any;
    if (threadIdx.x == 0) any = 0;
    __syncthreads();
    for (int i = threadIdx.x; i < 1024; i += blockDim.x)
        if (w[2 * i + 1] != 0) any = 1;
    __syncthreads();
    if (threadIdx.x == 0) g_is64 = (any == 0);
}

__global__ void k_extract(const void* __restrict__ ei, int E, int n) {
    int i = blockIdx.x * blockDim.x + threadIdx.x;
    if (i >= 2 * E) return;
    long long v = g_is64 ? ((const long long*)ei)[i]
                         : (long long)((const int*)ei)[i];
    int c = (int)v;
    c = (c < 0) ? 0 : ((c >= n) ? n - 1 : c);
    if (i < E) g_src[i] = c;
    else       g_dst[i - E] = c;
}

// --------------------------- CSR build -------------------------------------

__global__ void k_initcnt(int n) {
    int i = blockIdx.x * blockDim.x + threadIdx.x;
    if (i < n) { g_cnt[i] = 0; g_fill[i] = 0; }
}

__global__ void k_count(int E) {
    int e = blockIdx.x * blockDim.x + threadIdx.x;
    if (e < E) atomicAdd(&g_cnt[g_dst[e]], 1);
}

__global__ void k_scan_block(int n) {
    __shared__ int s[SCAN_B];
    int t = threadIdx.x;
    int i = blockIdx.x * SCAN_B + t;
    int v = (i < n) ? g_cnt[i] : 0;
    s[t] = v;
    __syncthreads();
#pragma unroll
    for (int off = 1; off < SCAN_B; off <<= 1) {
        int x = (t >= off) ? s[t - off] : 0;
        __syncthreads();
        s[t] += x;
        __syncthreads();
    }
    if (i < n) g_rowptr[i] = s[t] - v;
    if (t == SCAN_B - 1) g_bsum[blockIdx.x] = s[t];
}

__global__ void k_scan_sums(int nb) {
    __shared__ int s[64];
    int t = threadIdx.x;
    int v = (t < nb) ? g_bsum[t] : 0;
    s[t] = v;
    __syncthreads();
#pragma unroll
    for (int off = 1; off < 64; off <<= 1) {
        int x = (t >= off) ? s[t - off] : 0;
        __syncthreads();
        s[t] += x;
        __syncthreads();
    }
    if (t < nb) g_boff[t] = s[t] - v;
}

__global__ void k_scan_add(int n) {
    int i = blockIdx.x * blockDim.x + threadIdx.x;
    if (i < n) g_rowptr[i] += g_boff[i / SCAN_B];
}

__global__ void k_fill(int E) {
    int e = blockIdx.x * blockDim.x + threadIdx.x;
    if (e >= E) return;
    int d = g_dst[e];
    int pos = g_rowptr[d] + atomicAdd(&g_fill[d], 1);
    g_eidx[pos] = g_src[e];
}

// --------------------------- node prep / W split ----------------------------

__global__ void k_prep(const float* __restrict__ x, int n) {
    int w = (blockIdx.x * blockDim.x + threadIdx.x) >> 5;
    if (w >= n) return;
    int lane = threadIdx.x & 31;
    float d = rsqrtf((float)(g_cnt[w] + 1));
    if (lane == 0) g_dinv[w] = d;
    float4 v = ((const float4*)(x + (size_t)w * F1))[lane];
    ((float4*)(g_p1 + (size_t)w * F1))[lane] =
        make_float4(v.x * d, v.y * d, v.z * d, v.w * d);
}

// W [K][H] fp32 -> transposed [n][K] bf16 hi/lo
template <int K>
__global__ void k_splitW(const float* __restrict__ W,
                         __nv_bfloat16* __restrict__ Bh,
                         __nv_bfloat16* __restrict__ Bl) {
    int idx = blockIdx.x * blockDim.x + threadIdx.x;
    if (idx >= H * K) return;
    int c = idx / K, k = idx - c * K;
    __nv_bfloat16 h, l;
    split_bf16(W[(size_t)k * H + c], h, l);
    Bh[idx] = h;
    Bl[idx] = l;
}

// --------------------------- gather agg + fused split -----------------------

// acc = p[v] + sum p[u];  A1 = d[v]*acc -> split bf16 hi/lo
__global__ void k_agg1(int n) {
    int v = (blockIdx.x * blockDim.x + threadIdx.x) >> 5;
    if (v >= n) return;
    int lane = threadIdx.x & 31;
    float4 acc = ((const float4*)(g_p1 + (size_t)v * F1))[lane];
    int start = g_rowptr[v], end = start + g_cnt[v];
    for (int i = start; i < end; i++) {
        int u = g_eidx[i];
        float4 m = ((const float4*)(g_p1 + (size_t)u * F1))[lane];
        acc.x += m.x; acc.y += m.y; acc.z += m.z; acc.w += m.w;
    }
    float d = g_dinv[v];
    acc.x *= d; acc.y *= d; acc.z *= d; acc.w *= d;
    __nv_bfloat16 h0, l0, h1, l1, h2, l2, h3, l3;
    split_bf16(acc.x, h0, l0); split_bf16(acc.y, h1, l1);
    split_bf16(acc.z, h2, l2); split_bf16(acc.w, h3, l3);
    __nv_bfloat162* oh = (__nv_bfloat162*)(g_a1h + (size_t)v * F1);
    __nv_bfloat162* ol = (__nv_bfloat162*)(g_a1l + (size_t)v * F1);
    oh[lane * 2]     = __halves2bfloat162(h0, h1);
    oh[lane * 2 + 1] = __halves2bfloat162(h2, h3);
    ol[lane * 2]     = __halves2bfloat162(l0, l1);
    ol[lane * 2 + 1] = __halves2bfloat162(l2, l3);
}

__global__ void k_agg2(int n) {
    int v = (blockIdx.x * blockDim.x + threadIdx.x) >> 5;
    if (v >= n) return;
    int lane = threadIdx.x & 31;
    const float4* pr = (const float4*)(g_p2 + (size_t)v * H);
    float4 a0 = pr[lane];
    float4 a1 = pr[lane + 32];
    int start = g_rowptr[v], end = start + g_cnt[v];
    for (int i = start; i < end; i++) {
        int u = g_eidx[i];
        const float4* mr = (const float4*)(g_p2 + (size_t)u * H);
        float4 m0 = mr[lane], m1 = mr[lane + 32];
        a0.x += m0.x; a0.y += m0.y; a0.z += m0.z; a0.w += m0.w;
        a1.x += m1.x; a1.y += m1.y; a1.z += m1.z; a1.w += m1.w;
    }
    float d = g_dinv[v];
    a0.x *= d; a0.y *= d; a0.z *= d; a0.w *= d;
    a1.x *= d; a1.y *= d; a1.z *= d; a1.w *= d;
    __nv_bfloat162* oh = (__nv_bfloat162*)(g_a2h + (size_t)v * H);
    __nv_bfloat162* ol = (__nv_bfloat162*)(g_a2l + (size_t)v * H);
    __nv_bfloat16 h0, l0, h1, l1, h2, l2, h3, l3;
    split_bf16(a0.x, h0, l0); split_bf16(a0.y, h1, l1);
    split_bf16(a0.z, h2, l2); split_bf16(a0.w, h3, l3);
    oh[lane * 2]     = __halves2bfloat162(h0, h1);
    oh[lane * 2 + 1] = __halves2bfloat162(h2, h3);
    ol[lane * 2]     = __halves2bfloat162(l0, l1);
    ol[lane * 2 + 1] = __halves2bfloat162(l2, l3);
    split_bf16(a1.x, h0, l0); split_bf16(a1.y, h1, l1);
    split_bf16(a1.z, h2, l2); split_bf16(a1.w, h3, l3);
    oh[64 + lane * 2]     = __halves2bfloat162(h0, h1);
    oh[64 + lane * 2 + 1] = __halves2bfloat162(h2, h3);
    ol[64 + lane * 2]     = __halves2bfloat162(l0, l1);
    ol[64 + lane * 2 + 1] = __halves2bfloat162(l2, l3);
}

// ---------------------------------------------------------------------------
// Tensor-core GEMM on pre-split bf16 operands, cp.async double buffered.
// Block tile 128x128, BK=32, 8 warps (4M x 2N), warp tile 32x64.
// Smem per stage/part: [row][40] bf16 (20-word stride, conflict-free frags).
// EPI==1: p2 = d*relu(C+b1);  EPI==2: g_part[r][2*bx+warpN] = relu(C+b2)@Wfc
// ---------------------------------------------------------------------------

#define TILE_WORDS 2560                    // 128*40 bf16 = 2560 words
#define SMEM_GEMM  (8 * TILE_WORDS * 4)    // 8 buffers (2 stages x hi/lo x A/B)

__device__ __forceinline__ void mma_bf16(float* c, const uint32_t* a,
                                         uint32_t b0, uint32_t b1) {
    asm volatile(
        "mma.sync.aligned.m16n8k16.row.col.f32.bf16.bf16.f32 "
        "{%0,%1,%2,%3}, {%4,%5,%6,%7}, {%8,%9}, {%0,%1,%2,%3};\n"
        : "+f"(c[0]), "+f"(c[1]), "+f"(c[2]), "+f"(c[3])
        : "r"(a[0]), "r"(a[1]), "r"(a[2]), "r"(a[3]), "r"(b0), "r"(b1));
}

__device__ __forceinline__ void cpa16(uint32_t dst, const void* src) {
    asm volatile("cp.async.cg.shared.global [%0], [%1], 16;\n" :: "r"(dst), "l"(src));
}
__device__ __forceinline__ void cpa_commit() {
    asm volatile("cp.async.commit_group;\n");
}
template <int N>
__device__ __forceinline__ void cpa_wait() {
    asm volatile("cp.async.wait_group %0;\n" :: "n"(N));
}

template <int K, int EPI>
__global__ void __launch_bounds__(256)
k_gemm_tc(const __nv_bfloat16* __restrict__ Ah, const __nv_bfloat16* __restrict__ Al,
          const __nv_bfloat16* __restrict__ Bh, const __nv_bfloat16* __restrict__ Bl,
          const float* __restrict__ bias, const float* __restrict__ Wfc, int M) {
    const int NC = H;
    extern __shared__ __align__(16) uint32_t smem[];   // word-addressed

    int tid = threadIdx.x, lane = tid & 31, warp = tid >> 5;
    int warpM = warp & 3, warpN = warp >> 2;
    int rowBase = blockIdx.y * 128, colBase = blockIdx.x * 128;
    uint32_t sbase = (uint32_t)__cvta_generic_to_shared(smem);

    float acc[2][8][4];
#pragma unroll
    for (int mf = 0; mf < 2; mf++)
#pragma unroll
        for (int nf = 0; nf < 8; nf++)
#pragma unroll
            for (int i = 0; i < 4; i++) acc[mf][nf][i] = 0.0f;

    // per-thread copy coords: 512 16B-chunks per tile part, 2 per thread
    int c0 = tid * 2, c1 = tid * 2 + 1;
    int rA0 = c0 >> 2, cc0 = c0 & 3;
    int rA1 = c1 >> 2, cc1 = c1 & 3;

    auto load_stage = [&](int s, int k0) {
        // buffer word-offsets: A hi/lo = (s*2+p)*TILE, B hi/lo = (4+s*2+p)*TILE
        uint32_t ah = sbase + (uint32_t)((s * 2 + 0) * TILE_WORDS) * 4;
        uint32_t al = sbase + (uint32_t)((s * 2 + 1) * TILE_WORDS) * 4;
        uint32_t bh = sbase + (uint32_t)((4 + s * 2 + 0) * TILE_WORDS) * 4;
        uint32_t bl = sbase + (uint32_t)((4 + s * 2 + 1) * TILE_WORDS) * 4;
        uint32_t d0 = (uint32_t)(rA0 * 40 + cc0 * 8) * 2;   // byte offset
        uint32_t d1 = (uint32_t)(rA1 * 40 + cc1 * 8) * 2;
        const __nv_bfloat16* sA0 = Ah + (size_t)(rowBase + rA0) * K + k0 + cc0 * 8;
        const __nv_bfloat16* sA1 = Ah + (size_t)(rowBase + rA1) * K + k0 + cc1 * 8;
        const __nv_bfloat16* sAl0 = Al + (size_t)(rowBase + rA0) * K + k0 + cc0 * 8;
        const __nv_bfloat16* sAl1 = Al + (size_t)(rowBase + rA1) * K + k0 + cc1 * 8;
        const __nv_bfloat16* sB0 = Bh + (size_t)(colBase + rA0) * K + k0 + cc0 * 8;
        const __nv_bfloat16* sB1 = Bh + (size_t)(colBase + rA1) * K + k0 + cc1 * 8;
        const __nv_bfloat16* sBl0 = Bl + (size_t)(colBase + rA0) * K + k0 + cc0 * 8;
        const __nv_bfloat16* sBl1 = Bl + (size_t)(colBase + rA1) * K + k0 + cc1 * 8;
        cpa16(ah + d0, sA0);  cpa16(ah + d1, sA1);
        cpa16(al + d0, sAl0); cpa16(al + d1, sAl1);
        cpa16(bh + d0, sB0);  cpa16(bh + d1, sB1);
        cpa16(bl + d0, sBl0); cpa16(bl + d1, sBl1);
    };

    auto compute_stage = [&](int s) {
        const uint32_t* pAh = smem + (s * 2 + 0) * TILE_WORDS;
        const uint32_t* pAl = smem + (s * 2 + 1) * TILE_WORDS;
        const uint32_t* pBh = smem + (4 + s * 2 + 0) * TILE_WORDS;
        const uint32_t* pBl = smem + (4 + s * 2 + 1) * TILE_WORDS;
#pragma unroll
        for (int ks = 0; ks < 32; ks += 16) {
            int kw = (ks >> 1) + (lane & 3);
            uint32_t ah[2][4], al[2][4];
#pragma unroll
            for (int mf = 0; mf < 2; mf++) {
                int r0 = (warpM * 32 + mf * 16 + (lane >> 2)) * 20;
                int r1 = r0 + 8 * 20;
                ah[mf][0] = pAh[r0 + kw];     ah[mf][1] = pAh[r1 + kw];
                ah[mf][2] = pAh[r0 + kw + 4]; ah[mf][3] = pAh[r1 + kw + 4];
                al[mf][0] = pAl[r0 + kw];     al[mf][1] = pAl[r1 + kw];
                al[mf][2] = pAl[r0 + kw + 4]; al[mf][3] = pAl[r1 + kw + 4];
            }
#pragma unroll
            for (int nf = 0; nf < 8; nf++) {
                int nr = (warpN * 64 + nf * 8 + (lane >> 2)) * 20;
                uint32_t b0h = pBh[nr + kw], b1h = pBh[nr + kw + 4];
                uint32_t b0l = pBl[nr + kw], b1l = pBl[nr + kw + 4];
#pragma unroll
                for (int mf = 0; mf < 2; mf++) {
                    mma_bf16(acc[mf][nf], ah[mf], b0h, b1h);
                    mma_bf16(acc[mf][nf], ah[mf], b0l, b1l);
                    mma_bf16(acc[mf][nf], al[mf], b0h, b1h);
                }
            }
        }
    };

    const int T = K / 32;
    load_stage(0, 0);
    cpa_commit();
#pragma unroll 2
    for (int t = 0; t < T; t++) {
        if (t + 1 < T) {
            load_stage((t + 1) & 1, (t + 1) * 32);
            cpa_commit();
            cpa_wait<1>();
        } else {
            cpa_wait<0>();
        }
        __syncthreads();
        compute_stage(t & 1);
        __syncthreads();
    }

    // ---- epilogue
    if (EPI == 1) {
#pragma unroll
        for (int mf = 0; mf < 2; mf++)
#pragma unroll
            for (int rr = 0; rr < 2; rr++) {
                int r = rowBase + warpM * 32 + mf * 16 + (lane >> 2) + rr * 8;
                if (r >= M) continue;
                float d = g_dinv[r];
#pragma unroll
                for (int nf = 0; nf < 8; nf++) {
                    int c = colBase + warpN * 64 + nf * 8 + (lane & 3) * 2;
                    float v0 = fmaxf(acc[mf][nf][rr * 2 + 0] + bias[c], 0.f) * d;
                    float v1 = fmaxf(acc[mf][nf][rr * 2 + 1] + bias[c + 1], 0.f) * d;
                    *(float2*)&g_p2[(size_t)r * NC + c] = make_float2(v0, v1);
                }
            }
    } else {
#pragma unroll
        for (int mf = 0; mf < 2; mf++)
#pragma unroll
            for (int rr = 0; rr < 2; rr++) {
                float p = 0.0f;
#pragma unroll
                for (int nf = 0; nf < 8; nf++) {
                    int c = colBase + warpN * 64 + nf * 8 + (lane & 3) * 2;
                    p += fmaxf(acc[mf][nf][rr * 2 + 0] + bias[c], 0.f) * Wfc[c];
                    p += fmaxf(acc[mf][nf][rr * 2 + 1] + bias[c + 1], 0.f) * Wfc[c + 1];
                }
                p += __shfl_xor_sync(0xFFFFFFFFu, p, 1);
                p += __shfl_xor_sync(0xFFFFFFFFu, p, 2);
                int r = rowBase + warpM * 32 + mf * 16 + (lane >> 2) + rr * 8;
                if ((lane & 3) == 0 && r < M)
                    g_part[(size_t)r * 4 + blockIdx.x * 2 + warpN] = p;
            }
    }
}

__global__ void k_final(const float* __restrict__ bfc, float* __restrict__ out, int n) {
    int i = blockIdx.x * blockDim.x + threadIdx.x;
    if (i < n)
        out[i] = g_part[(size_t)i * 4] + g_part[(size_t)i * 4 + 1]
               + g_part[(size_t)i * 4 + 2] + g_part[(size_t)i * 4 + 3] + bfc[0];
}

// ---------------------------------------------------------------------------

extern "C" void kernel_launch(void* const* d_in, const int* in_sizes, int n_in,
                              void* d_out, int out_size) {
    const float* x   = (const float*)d_in[0];
    const void*  ei  = d_in[1];
    const float* W1  = (const float*)d_in[2];
    const float* b1  = (const float*)d_in[3];
    const float* W2  = (const float*)d_in[4];
    const float* b2  = (const float*)d_in[5];
    const float* Wfc = (const float*)d_in[6];
    const float* bfc = (const float*)d_in[7];
    float*       out = (float*)d_out;

    int h   = in_sizes[3];            // 256
    int fin = in_sizes[2] / h;        // 128
    int n   = in_sizes[0] / fin;      // 50000
    int E   = in_sizes[1] / 2;        // 800000
    (void)h; (void)n_in; (void)out_size;

    int nb = (n + SCAN_B - 1) / SCAN_B;

    cudaFuncSetAttribute(k_gemm_tc<F1, 1>,
                         cudaFuncAttributeMaxDynamicSharedMemorySize, SMEM_GEMM);
    cudaFuncSetAttribute(k_gemm_tc<H, 2>,
                         cudaFuncAttributeMaxDynamicSharedMemorySize, SMEM_GEMM);

    // device pointers to __device__ globals are directly usable in launches
    __nv_bfloat16 *a1h, *a1l, *a2h, *a2l, *w1h, *w1l, *w2h, *w2l;
    cudaGetSymbolAddress((void**)&a1h, g_a1h);
    cudaGetSymbolAddress((void**)&a1l, g_a1l);
    cudaGetSymbolAddress((void**)&a2h, g_a2h);
    cudaGetSymbolAddress((void**)&a2l, g_a2l);
    cudaGetSymbolAddress((void**)&w1h, g_w1h);
    cudaGetSymbolAddress((void**)&w1l, g_w1l);
    cudaGetSymbolAddress((void**)&w2h, g_w2h);
    cudaGetSymbolAddress((void**)&w2l, g_w2l);

    k_detect <<<1, 256>>>((const int*)ei);
    k_extract<<<(2 * E + 255) / 256, 256>>>(ei, E, n);

    k_initcnt<<<(n + 255) / 256, 256>>>(n);
    k_count  <<<(E + 255) / 256, 256>>>(E);
    k_scan_block<<<nb, SCAN_B>>>(n);
    k_scan_sums<<<1, 64>>>(nb);
    k_scan_add<<<(n + 255) / 256, 256>>>(n);
    k_fill   <<<(E + 255) / 256, 256>>>(E);

    k_splitW<F1><<<(H * F1 + 255) / 256, 256>>>(W1, w1h, w1l);
    k_splitW<H> <<<(H * H  + 255) / 256, 256>>>(W2, w2h, w2l);

    k_prep<<<(n * 32 + 255) / 256, 256>>>(x, n);
    k_agg1<<<(n * 32 + 255) / 256, 256>>>(n);

    dim3 gg(2, (n + 127) / 128);
    k_gemm_tc<F1, 1><<<gg, 256, SMEM_GEMM>>>(a1h, a1l, w1h, w1l, b1, nullptr, n);
    k_agg2<<<(n * 32 + 255) / 256, 256>>>(n);
    k_gemm_tc<H, 2><<<gg, 256, SMEM_GEMM>>>(a2h, a2l, w2h, w2l, b2, Wfc, n);
    k_final<<<(n + 255) / 256, 256>>>(bfc, out, n);
}

// round 11
// speedup vs baseline: 2.2061x; 1.0125x over previous
#include <cuda_runtime.h>
#include <cuda_bf16.h>
#include <cstdint>

// ---------------------------------------------------------------------------
// GCN: out = relu(Â X W1 + b1) -> relu(Â H W2 + b2) -> @Wfc + bfc
// Aggregate-first + CSR gather; GEMM operands pre-split to bf16 hi/lo
// (3-term mma.sync emulation ~1e-5); cp.async double-buffer + ldmatrix frags.
// ---------------------------------------------------------------------------

#define NMAX   50176
#define EMAX   1048576
#define F1     128
#define H      256
#define SCAN_B 1024

__device__ int   g_is64;
__device__ int   g_src   [EMAX];
__device__ int   g_dst   [EMAX];
__device__ int   g_cnt   [NMAX];
__device__ int   g_fill  [NMAX];
__device__ int   g_rowptr[NMAX];
__device__ int   g_eidx  [EMAX];
__device__ int   g_bsum  [64];
__device__ int   g_boff  [64];
__device__ float g_dinv  [NMAX];
__device__ float g_p1  [(size_t)NMAX * F1];     // d[u]*x[u]
__device__ float g_p2  [(size_t)NMAX * H];      // d[u]*h1[u]
__device__ float g_part[(size_t)NMAX * 4];

// pre-split bf16 operands (16B aligned for cp.async)
__device__ __align__(16) __nv_bfloat16 g_a1h[(size_t)NMAX * F1];
__device__ __align__(16) __nv_bfloat16 g_a1l[(size_t)NMAX * F1];
__device__ __align__(16) __nv_bfloat16 g_a2h[(size_t)NMAX * H];
__device__ __align__(16) __nv_bfloat16 g_a2l[(size_t)NMAX * H];
__device__ __align__(16) __nv_bfloat16 g_w1h[(size_t)H * F1];   // [n][k] transposed
__device__ __align__(16) __nv_bfloat16 g_w1l[(size_t)H * F1];
__device__ __align__(16) __nv_bfloat16 g_w2h[(size_t)H * H];
__device__ __align__(16) __nv_bfloat16 g_w2l[(size_t)H * H];

__device__ __forceinline__ void split_bf16(float x, __nv_bfloat16& h, __nv_bfloat16& l) {
    h = __float2bfloat16_rn(x);
    l = __float2bfloat16_rn(x - __bfloat162float(h));
}

// --------------------------- edge ingest -----------------------------------

__global__ void k_detect(const int* __restrict__ w) {
    __shared__ int any;
    if (threadIdx.x == 0) any = 0;
    __syncthreads();
    for (int i = threadIdx.x; i < 1024; i += blockDim.x)
        if (w[2 * i + 1] != 0) any = 1;
    __syncthreads();
    if (threadIdx.x == 0) g_is64 = (any == 0);
}

// decode + fused degree count (g_cnt must be zeroed first)
__global__ void k_extract(const void* __restrict__ ei, int E, int n) {
    int i = blockIdx.x * blockDim.x + threadIdx.x;
    if (i >= 2 * E) return;
    long long v = g_is64 ? ((const long long*)ei)[i]
                         : (long long)((const int*)ei)[i];
    int c = (int)v;
    c = (c < 0) ? 0 : ((c >= n) ? n - 1 : c);
    if (i < E) {
        g_src[i] = c;
    } else {
        g_dst[i - E] = c;
        atomicAdd(&g_cnt[c], 1);
    }
}

// --------------------------- CSR build -------------------------------------

__global__ void k_initcnt(int n) {
    int i = blockIdx.x * blockDim.x + threadIdx.x;
    if (i < n) { g_cnt[i] = 0; g_fill[i] = 0; }
}

__global__ void k_scan_block(int n) {
    __shared__ int s[SCAN_B];
    int t = threadIdx.x;
    int i = blockIdx.x * SCAN_B + t;
    int v = (i < n) ? g_cnt[i] : 0;
    s[t] = v;
    __syncthreads();
#pragma unroll
    for (int off = 1; off < SCAN_B; off <<= 1) {
        int x = (t >= off) ? s[t - off] : 0;
        __syncthreads();
        s[t] += x;
        __syncthreads();
    }
    if (i < n) g_rowptr[i] = s[t] - v;
    if (t == SCAN_B - 1) g_bsum[blockIdx.x] = s[t];
}

__global__ void k_scan_sums(int nb) {
    __shared__ int s[64];
    int t = threadIdx.x;
    int v = (t < nb) ? g_bsum[t] : 0;
    s[t] = v;
    __syncthreads();
#pragma unroll
    for (int off = 1; off < 64; off <<= 1) {
        int x = (t >= off) ? s[t - off] : 0;
        __syncthreads();
        s[t] += x;
        __syncthreads();
    }
    if (t < nb) g_boff[t] = s[t] - v;
}

__global__ void k_scan_add(int n) {
    int i = blockIdx.x * blockDim.x + threadIdx.x;
    if (i < n) g_rowptr[i] += g_boff[i / SCAN_B];
}

__global__ void k_fill(int E) {
    int e = blockIdx.x * blockDim.x + threadIdx.x;
    if (e >= E) return;
    int d = g_dst[e];
    int pos = g_rowptr[d] + atomicAdd(&g_fill[d], 1);
    g_eidx[pos] = g_src[e];
}

// --------------------------- node prep / W split ----------------------------

__global__ void k_prep(const float* __restrict__ x, int n) {
    int w = (blockIdx.x * blockDim.x + threadIdx.x) >> 5;
    if (w >= n) return;
    int lane = threadIdx.x & 31;
    float d = rsqrtf((float)(g_cnt[w] + 1));
    if (lane == 0) g_dinv[w] = d;
    float4 v = ((const float4*)(x + (size_t)w * F1))[lane];
    ((float4*)(g_p1 + (size_t)w * F1))[lane] =
        make_float4(v.x * d, v.y * d, v.z * d, v.w * d);
}

// W [K][H] fp32 -> transposed [n][K] bf16 hi/lo
template <int K>
__global__ void k_splitW(const float* __restrict__ W,
                         __nv_bfloat16* __restrict__ Bh,
                         __nv_bfloat16* __restrict__ Bl) {
    int idx = blockIdx.x * blockDim.x + threadIdx.x;
    if (idx >= H * K) return;
    int c = idx / K, k = idx - c * K;
    __nv_bfloat16 h, l;
    split_bf16(W[(size_t)k * H + c], h, l);
    Bh[idx] = h;
    Bl[idx] = l;
}

// --------------------------- gather agg + fused split -----------------------

// acc = p[v] + sum p[u];  A1 = d[v]*acc -> split bf16 hi/lo.  2x unrolled.
__global__ void k_agg1(int n) {
    int v = (blockIdx.x * blockDim.x + threadIdx.x) >> 5;
    if (v >= n) return;
    int lane = threadIdx.x & 31;
    float4 acc = ((const float4*)(g_p1 + (size_t)v * F1))[lane];
    int i = g_rowptr[v], end = i + g_cnt[v];
    for (; i + 1 < end; i += 2) {
        int u0 = g_eidx[i], u1 = g_eidx[i + 1];
        float4 m0 = ((const float4*)(g_p1 + (size_t)u0 * F1))[lane];
        float4 m1 = ((const float4*)(g_p1 + (size_t)u1 * F1))[lane];
        acc.x += m0.x + m1.x; acc.y += m0.y + m1.y;
        acc.z += m0.z + m1.z; acc.w += m0.w + m1.w;
    }
    if (i < end) {
        int u = g_eidx[i];
        float4 m = ((const float4*)(g_p1 + (size_t)u * F1))[lane];
        acc.x += m.x; acc.y += m.y; acc.z += m.z; acc.w += m.w;
    }
    float d = g_dinv[v];
    acc.x *= d; acc.y *= d; acc.z *= d; acc.w *= d;
    __nv_bfloat16 h0, l0, h1, l1, h2, l2, h3, l3;
    split_bf16(acc.x, h0, l0); split_bf16(acc.y, h1, l1);
    split_bf16(acc.z, h2, l2); split_bf16(acc.w, h3, l3);
    __nv_bfloat162* oh = (__nv_bfloat162*)(g_a1h + (size_t)v * F1);
    __nv_bfloat162* ol = (__nv_bfloat162*)(g_a1l + (size_t)v * F1);
    oh[lane * 2]     = __halves2bfloat162(h0, h1);
    oh[lane * 2 + 1] = __halves2bfloat162(h2, h3);
    ol[lane * 2]     = __halves2bfloat162(l0, l1);
    ol[lane * 2 + 1] = __halves2bfloat162(l2, l3);
}

__global__ void k_agg2(int n) {
    int v = (blockIdx.x * blockDim.x + threadIdx.x) >> 5;
    if (v >= n) return;
    int lane = threadIdx.x & 31;
    const float4* pr = (const float4*)(g_p2 + (size_t)v * H);
    float4 a0 = pr[lane];
    float4 a1 = pr[lane + 32];
    int i = g_rowptr[v], end = i + g_cnt[v];
    for (; i + 1 < end; i += 2) {
        int u0 = g_eidx[i], u1 = g_eidx[i + 1];
        const float4* r0 = (const float4*)(g_p2 + (size_t)u0 * H);
        const float4* r1 = (const float4*)(g_p2 + (size_t)u1 * H);
        float4 m00 = r0[lane], m01 = r0[lane + 32];
        float4 m10 = r1[lane], m11 = r1[lane + 32];
        a0.x += m00.x + m10.x; a0.y += m00.y + m10.y;
        a0.z += m00.z + m10.z; a0.w += m00.w + m10.w;
        a1.x += m01.x + m11.x; a1.y += m01.y + m11.y;
        a1.z += m01.z + m11.z; a1.w += m01.w + m11.w;
    }
    if (i < end) {
        int u = g_eidx[i];
        const float4* mr = (const float4*)(g_p2 + (size_t)u * H);
        float4 m0 = mr[lane], m1 = mr[lane + 32];
        a0.x += m0.x; a0.y += m0.y; a0.z += m0.z; a0.w += m0.w;
        a1.x += m1.x; a1.y += m1.y; a1.z += m1.z; a1.w += m1.w;
    }
    float d = g_dinv[v];
    a0.x *= d; a0.y *= d; a0.z *= d; a0.w *= d;
    a1.x *= d; a1.y *= d; a1.z *= d; a1.w *= d;
    __nv_bfloat162* oh = (__nv_bfloat162*)(g_a2h + (size_t)v * H);
    __nv_bfloat162* ol = (__nv_bfloat162*)(g_a2l + (size_t)v * H);
    __nv_bfloat16 h0, l0, h1, l1, h2, l2, h3, l3;
    split_bf16(a0.x, h0, l0); split_bf16(a0.y, h1, l1);
    split_bf16(a0.z, h2, l2); split_bf16(a0.w, h3, l3);
    oh[lane * 2]     = __halves2bfloat162(h0, h1);
    oh[lane * 2 + 1] = __halves2bfloat162(h2, h3);
    ol[lane * 2]     = __halves2bfloat162(l0, l1);
    ol[lane * 2 + 1] = __halves2bfloat162(l2, l3);
    split_bf16(a1.x, h0, l0); split_bf16(a1.y, h1, l1);
    split_bf16(a1.z, h2, l2); split_bf16(a1.w, h3, l3);
    oh[64 + lane * 2]     = __halves2bfloat162(h0, h1);
    oh[64 + lane * 2 + 1] = __halves2bfloat162(h2, h3);
    ol[64 + lane * 2]     = __halves2bfloat162(l0, l1);
    ol[64 + lane * 2 + 1] = __halves2bfloat162(l2, l3);
}

// ---------------------------------------------------------------------------
// Tensor-core GEMM on pre-split bf16 operands, cp.async double buffered,
// ldmatrix.x4 fragment loads (12 LDSM per 16-k step vs 48 scalar LDS).
// Block tile 128x128, BK=32, 8 warps (4M x 2N), warp tile 32x64.
// Smem [row][40 bf16] (80B stride: ldmatrix rows hit distinct banks).
// EPI==1: p2 = d*relu(C+b1);  EPI==2: g_part[r][2*bx+warpN] = relu(C+b2)@Wfc
// ---------------------------------------------------------------------------

#define TILE_WORDS 2560                    // 128*40 bf16 = 2560 words
#define TILE_BYTES (TILE_WORDS * 4)
#define SMEM_GEMM  (8 * TILE_BYTES)        // 8 buffers (2 stages x hi/lo x A/B)

__device__ __forceinline__ void mma_bf16(float* c, const uint32_t* a,
                                         uint32_t b0, uint32_t b1) {
    asm volatile(
        "mma.sync.aligned.m16n8k16.row.col.f32.bf16.bf16.f32 "
        "{%0,%1,%2,%3}, {%4,%5,%6,%7}, {%8,%9}, {%0,%1,%2,%3};\n"
        : "+f"(c[0]), "+f"(c[1]), "+f"(c[2]), "+f"(c[3])
        : "r"(a[0]), "r"(a[1]), "r"(a[2]), "r"(a[3]), "r"(b0), "r"(b1));
}

__device__ __forceinline__ void ldm_x4(uint32_t* r, uint32_t addr) {
    asm volatile(
        "ldmatrix.sync.aligned.m8n8.x4.shared.b16 {%0,%1,%2,%3}, [%4];\n"
        : "=r"(r[0]), "=r"(r[1]), "=r"(r[2]), "=r"(r[3]) : "r"(addr));
}

__device__ __forceinline__ void cpa16(uint32_t dst, const void* src) {
    asm volatile("cp.async.cg.shared.global [%0], [%1], 16;\n" :: "r"(dst), "l"(src));
}
__device__ __forceinline__ void cpa_commit() {
    asm volatile("cp.async.commit_group;\n");
}
template <int N>
__device__ __forceinline__ void cpa_wait() {
    asm volatile("cp.async.wait_group %0;\n" :: "n"(N));
}

template <int K, int EPI>
__global__ void __launch_bounds__(256)
k_gemm_tc(const __nv_bfloat16* __restrict__ Ah, const __nv_bfloat16* __restrict__ Al,
          const __nv_bfloat16* __restrict__ Bh, const __nv_bfloat16* __restrict__ Bl,
          const float* __restrict__ bias, const float* __restrict__ Wfc, int M) {
    const int NC = H;
    extern __shared__ __align__(16) uint32_t smem[];

    int tid = threadIdx.x, lane = tid & 31, warp = tid >> 5;
    int warpM = warp & 3, warpN = warp >> 2;
    int rowBase = blockIdx.y * 128, colBase = blockIdx.x * 128;
    uint32_t sbase = (uint32_t)__cvta_generic_to_shared(smem);

    float acc[2][8][4];
#pragma unroll
    for (int mf = 0; mf < 2; mf++)
#pragma unroll
        for (int nf = 0; nf < 8; nf++)
#pragma unroll
            for (int i = 0; i < 4; i++) acc[mf][nf][i] = 0.0f;

    // per-thread copy coords: 512 16B-chunks per tile part, 2 per thread
    int c0 = tid * 2, c1 = tid * 2 + 1;
    int rA0 = c0 >> 2, cc0 = c0 & 3;
    int rA1 = c1 >> 2, cc1 = c1 & 3;

    auto load_stage = [&](int s, int k0) {
        uint32_t ah = sbase + (uint32_t)(s * 2 + 0) * TILE_BYTES;
        uint32_t al = sbase + (uint32_t)(s * 2 + 1) * TILE_BYTES;
        uint32_t bh = sbase + (uint32_t)(4 + s * 2 + 0) * TILE_BYTES;
        uint32_t bl = sbase + (uint32_t)(4 + s * 2 + 1) * TILE_BYTES;
        uint32_t d0 = (uint32_t)(rA0 * 40 + cc0 * 8) * 2;
        uint32_t d1 = (uint32_t)(rA1 * 40 + cc1 * 8) * 2;
        cpa16(ah + d0, Ah + (size_t)(rowBase + rA0) * K + k0 + cc0 * 8);
        cpa16(ah + d1, Ah + (size_t)(rowBase + rA1) * K + k0 + cc1 * 8);
        cpa16(al + d0, Al + (size_t)(rowBase + rA0) * K + k0 + cc0 * 8);
        cpa16(al + d1, Al + (size_t)(rowBase + rA1) * K + k0 + cc1 * 8);
        cpa16(bh + d0, Bh + (size_t)(colBase + rA0) * K + k0 + cc0 * 8);
        cpa16(bh + d1, Bh + (size_t)(colBase + rA1) * K + k0 + cc1 * 8);
        cpa16(bl + d0, Bl + (size_t)(colBase + rA0) * K + k0 + cc0 * 8);
        cpa16(bl + d1, Bl + (size_t)(colBase + rA1) * K + k0 + cc1 * 8);
    };

    auto compute_stage = [&](int s) {
        uint32_t aBh = sbase + (uint32_t)(s * 2 + 0) * TILE_BYTES;
        uint32_t aBl = sbase + (uint32_t)(s * 2 + 1) * TILE_BYTES;
        uint32_t bBh = sbase + (uint32_t)(4 + s * 2 + 0) * TILE_BYTES;
        uint32_t bBl = sbase + (uint32_t)(4 + s * 2 + 1) * TILE_BYTES;
        // ldmatrix lane-address offsets
        uint32_t aoff = (uint32_t)(warpM * 32 + (lane & 15)) * 80 + (lane >> 4) * 16;
        uint32_t boff = (uint32_t)(warpN * 64 + ((lane >> 4) << 3) + (lane & 7)) * 80
                      + ((lane >> 3) & 1) * 16;
#pragma unroll
        for (int ks = 0; ks < 2; ks++) {           // two 16-k steps
            uint32_t kb = ks * 32;                 // 16 bf16 = 32 bytes
            uint32_t ah[2][4], al[2][4], bhf[4][4], blf[4][4];
#pragma unroll
            for (int mf = 0; mf < 2; mf++) {
                ldm_x4(ah[mf], aBh + aoff + mf * (16 * 80) + kb);
                ldm_x4(al[mf], aBl + aoff + mf * (16 * 80) + kb);
            }
#pragma unroll
            for (int nfp = 0; nfp < 4; nfp++) {
                ldm_x4(bhf[nfp], bBh + boff + nfp * (16 * 80) + kb);
                ldm_x4(blf[nfp], bBl + boff + nfp * (16 * 80) + kb);
            }
#pragma unroll
            for (int nf = 0; nf < 8; nf++) {
                uint32_t b0h = bhf[nf >> 1][(nf & 1) * 2], b1h = bhf[nf >> 1][(nf & 1) * 2 + 1];
                uint32_t b0l = blf[nf >> 1][(nf & 1) * 2], b1l = blf[nf >> 1][(nf & 1) * 2 + 1];
#pragma unroll
                for (int mf = 0; mf < 2; mf++) {
                    mma_bf16(acc[mf][nf], ah[mf], b0h, b1h);
                    mma_bf16(acc[mf][nf], ah[mf], b0l, b1l);
                    mma_bf16(acc[mf][nf], al[mf], b0h, b1h);
                }
            }
        }
    };

    const int T = K / 32;
    load_stage(0, 0);
    cpa_commit();
#pragma unroll 2
    for (int t = 0; t < T; t++) {
        if (t + 1 < T) {
            load_stage((t + 1) & 1, (t + 1) * 32);
            cpa_commit();
            cpa_wait<1>();
        } else {
            cpa_wait<0>();
        }
        __syncthreads();
        compute_stage(t & 1);
        __syncthreads();
    }

    // ---- epilogue
    if (EPI == 1) {
#pragma unroll
        for (int mf = 0; mf < 2; mf++)
#pragma unroll
            for (int rr = 0; rr < 2; rr++) {
                int r = rowBase + warpM * 32 + mf * 16 + (lane >> 2) + rr * 8;
                if (r >= M) continue;
                float d = g_dinv[r];
#pragma unroll
                for (int nf = 0; nf < 8; nf++) {
                    int c = colBase + warpN * 64 + nf * 8 + (lane & 3) * 2;
                    float v0 = fmaxf(acc[mf][nf][rr * 2 + 0] + bias[c], 0.f) * d;
                    float v1 = fmaxf(acc[mf][nf][rr * 2 + 1] + bias[c + 1], 0.f) * d;
                    *(float2*)&g_p2[(size_t)r * NC + c] = make_float2(v0, v1);
                }
            }
    } else {
#pragma unroll
        for (int mf = 0; mf < 2; mf++)
#pragma unroll
            for (int rr = 0; rr < 2; rr++) {
                float p = 0.0f;
#pragma unroll
                for (int nf = 0; nf < 8; nf++) {
                    int c = colBase + warpN * 64 + nf * 8 + (lane & 3) * 2;
                    p += fmaxf(acc[mf][nf][rr * 2 + 0] + bias[c], 0.f) * Wfc[c];
                    p += fmaxf(acc[mf][nf][rr * 2 + 1] + bias[c + 1], 0.f) * Wfc[c + 1];
                }
                p += __shfl_xor_sync(0xFFFFFFFFu, p, 1);
                p += __shfl_xor_sync(0xFFFFFFFFu, p, 2);
                int r = rowBase + warpM * 32 + mf * 16 + (lane >> 2) + rr * 8;
                if ((lane & 3) == 0 && r < M)
                    g_part[(size_t)r * 4 + blockIdx.x * 2 + warpN] = p;
            }
    }
}

__global__ void k_final(const float* __restrict__ bfc, float* __restrict__ out, int n) {
    int i = blockIdx.x * blockDim.x + threadIdx.x;
    if (i < n)
        out[i] = g_part[(size_t)i * 4] + g_part[(size_t)i * 4 + 1]
               + g_part[(size_t)i * 4 + 2] + g_part[(size_t)i * 4 + 3] + bfc[0];
}

// ---------------------------------------------------------------------------

extern "C" void kernel_launch(void* const* d_in, const int* in_sizes, int n_in,
                              void* d_out, int out_size) {
    const float* x   = (const float*)d_in[0];
    const void*  ei  = d_in[1];
    const float* W1  = (const float*)d_in[2];
    const float* b1  = (const float*)d_in[3];
    const float* W2  = (const float*)d_in[4];
    const float* b2  = (const float*)d_in[5];
    const float* Wfc = (const float*)d_in[6];
    const float* bfc = (const float*)d_in[7];
    float*       out = (float*)d_out;

    int h   = in_sizes[3];            // 256
    int fin = in_sizes[2] / h;        // 128
    int n   = in_sizes[0] / fin;      // 50000
    int E   = in_sizes[1] / 2;        // 800000
    (void)h; (void)n_in; (void)out_size;

    int nb = (n + SCAN_B - 1) / SCAN_B;

    cudaFuncSetAttribute(k_gemm_tc<F1, 1>,
                         cudaFuncAttributeMaxDynamicSharedMemorySize, SMEM_GEMM);
    cudaFuncSetAttribute(k_gemm_tc<H, 2>,
                         cudaFuncAttributeMaxDynamicSharedMemorySize, SMEM_GEMM);

    __nv_bfloat16 *a1h, *a1l, *a2h, *a2l, *w1h, *w1l, *w2h, *w2l;
    cudaGetSymbolAddress((void**)&a1h, g_a1h);
    cudaGetSymbolAddress((void**)&a1l, g_a1l);
    cudaGetSymbolAddress((void**)&a2h, g_a2h);
    cudaGetSymbolAddress((void**)&a2l, g_a2l);
    cudaGetSymbolAddress((void**)&w1h, g_w1h);
    cudaGetSymbolAddress((void**)&w1l, g_w1l);
    cudaGetSymbolAddress((void**)&w2h, g_w2h);
    cudaGetSymbolAddress((void**)&w2l, g_w2l);

    k_detect <<<1, 256>>>((const int*)ei);
    k_initcnt<<<(n + 255) / 256, 256>>>(n);
    k_extract<<<(2 * E + 255) / 256, 256>>>(ei, E, n);   // fused degree count

    k_scan_block<<<nb, SCAN_B>>>(n);
    k_scan_sums<<<1, 64>>>(nb);
    k_scan_add<<<(n + 255) / 256, 256>>>(n);
    k_fill   <<<(E + 255) / 256, 256>>>(E);

    k_splitW<F1><<<(H * F1 + 255) / 256, 256>>>(W1, w1h, w1l);
    k_splitW<H> <<<(H * H  + 255) / 256, 256>>>(W2, w2h, w2l);

    k_prep<<<(n * 32 + 255) / 256, 256>>>(x, n);
    k_agg1<<<(n * 32 + 255) / 256, 256>>>(n);

    dim3 gg(2, (n + 127) / 128);
    k_gemm_tc<F1, 1><<<gg, 256, SMEM_GEMM>>>(a1h, a1l, w1h, w1l, b1, nullptr, n);
    k_agg2<<<(n * 32 + 255) / 256, 256>>>(n);
    k_gemm_tc<H, 2><<<gg, 256, SMEM_GEMM>>>(a2h, a2l, w2h, w2l, b2, Wfc, n);
    k_final<<<(n + 255) / 256, 256>>>(bfc, out, n);
}

// round 13
// speedup vs baseline: 2.3830x; 1.0802x over previous
#include <cuda_runtime.h>
#include <cuda_bf16.h>
#include <cstdint>

// ---------------------------------------------------------------------------
// GCN: out = relu(Â X W1 + b1) -> relu(Â H W2 + b2) -> @Wfc + bfc
// Aggregate-first + CSR gather; GEMM operands pre-split to bf16 hi/lo
// (3-term mma.sync emulation ~1e-5); cp.async double-buffer + ldmatrix frags.
// N=256 full-width GEMM tiles (A read once; layer-2 writes out directly).
// ---------------------------------------------------------------------------

#define NMAX   50176
#define EMAX   1048576
#define F1     128
#define H      256
#define SCAN_B 1024

__device__ int   g_is64;
__device__ int   g_src   [EMAX];
__device__ int   g_dst   [EMAX];
__device__ int   g_cnt   [NMAX];
__device__ int   g_fill  [NMAX];
__device__ int   g_rowptr[NMAX];
__device__ int   g_eidx  [EMAX];
__device__ int   g_bsum  [64];
__device__ int   g_boff  [64];
__device__ float g_dinv  [NMAX];
__device__ float g_p1  [(size_t)NMAX * F1];     // d[u]*x[u]
__device__ float g_p2  [(size_t)NMAX * H];      // d[u]*h1[u]

// pre-split bf16 operands (16B aligned for cp.async)
__device__ __align__(16) __nv_bfloat16 g_a1h[(size_t)NMAX * F1];
__device__ __align__(16) __nv_bfloat16 g_a1l[(size_t)NMAX * F1];
__device__ __align__(16) __nv_bfloat16 g_a2h[(size_t)NMAX * H];
__device__ __align__(16) __nv_bfloat16 g_a2l[(size_t)NMAX * H];
__device__ __align__(16) __nv_bfloat16 g_w1h[(size_t)H * F1];   // [n][K]
__device__ __align__(16) __nv_bfloat16 g_w1l[(size_t)H * F1];
__device__ __align__(16) __nv_bfloat16 g_w2h[(size_t)H * H];
__device__ __align__(16) __nv_bfloat16 g_w2l[(size_t)H * H];

__device__ __forceinline__ void split_bf16(float x, __nv_bfloat16& h, __nv_bfloat16& l) {
    h = __float2bfloat16_rn(x);
    l = __float2bfloat16_rn(x - __bfloat162float(h));
}

// --------------------------- edge ingest + init -----------------------------

// merged: zero cnt/fill arrays + dtype detect (block 0)
__global__ void k_detect_init(const int* __restrict__ w, int n) {
    int i = blockIdx.x * blockDim.x + threadIdx.x;
    if (i < n) { g_cnt[i] = 0; g_fill[i] = 0; }
    if (blockIdx.x == 0) {
        __shared__ int any;
        if (threadIdx.x == 0) any = 0;
        __syncthreads();
        for (int j = threadIdx.x; j < 1024; j += blockDim.x)
            if (w[2 * j + 1] != 0) any = 1;
        __syncthreads();
        if (threadIdx.x == 0) g_is64 = (any == 0);
    }
}

// decode + fused degree count
__global__ void k_extract(const void* __restrict__ ei, int E, int n) {
    int i = blockIdx.x * blockDim.x + threadIdx.x;
    if (i >= 2 * E) return;
    long long v = g_is64 ? ((const long long*)ei)[i]
                         : (long long)((const int*)ei)[i];
    int c = (int)v;
    c = (c < 0) ? 0 : ((c >= n) ? n - 1 : c);
    if (i < E) {
        g_src[i] = c;
    } else {
        g_dst[i - E] = c;
        atomicAdd(&g_cnt[c], 1);
    }
}

// --------------------------- CSR build -------------------------------------

__global__ void k_scan_block(int n) {
    __shared__ int s[SCAN_B];
    int t = threadIdx.x;
    int i = blockIdx.x * SCAN_B + t;
    int v = (i < n) ? g_cnt[i] : 0;
    s[t] = v;
    __syncthreads();
#pragma unroll
    for (int off = 1; off < SCAN_B; off <<= 1) {
        int x = (t >= off) ? s[t - off] : 0;
        __syncthreads();
        s[t] += x;
        __syncthreads();
    }
    if (i < n) g_rowptr[i] = s[t] - v;          // pre-offset exclusive
    if (t == SCAN_B - 1) g_bsum[blockIdx.x] = s[t];
}

__global__ void k_scan_sums(int nb) {
    __shared__ int s[64];
    int t = threadIdx.x;
    int v = (t < nb) ? g_bsum[t] : 0;
    s[t] = v;
    __syncthreads();
#pragma unroll
    for (int off = 1; off < 64; off <<= 1) {
        int x = (t >= off) ? s[t - off] : 0;
        __syncthreads();
        s[t] += x;
        __syncthreads();
    }
    if (t < nb) g_boff[t] = s[t] - v;
}

// rowptr(final)[d] = g_rowptr[d] + g_boff[d >> 10], computed inline by users
__global__ void k_fill(int E) {
    int e = blockIdx.x * blockDim.x + threadIdx.x;
    if (e >= E) return;
    int d = g_dst[e];
    int pos = g_rowptr[d] + g_boff[d >> 10] + atomicAdd(&g_fill[d], 1);
    g_eidx[pos] = g_src[e];
}

// --------------------------- node prep / W split ----------------------------

__global__ void k_prep(const float* __restrict__ x, int n) {
    int w = (blockIdx.x * blockDim.x + threadIdx.x) >> 5;
    if (w >= n) return;
    int lane = threadIdx.x & 31;
    float d = rsqrtf((float)(g_cnt[w] + 1));
    if (lane == 0) g_dinv[w] = d;
    float4 v = ((const float4*)(x + (size_t)w * F1))[lane];
    ((float4*)(g_p1 + (size_t)w * F1))[lane] =
        make_float4(v.x * d, v.y * d, v.z * d, v.w * d);
}

template <int K>
__global__ void k_splitW(const float* __restrict__ W,
                         __nv_bfloat16* __restrict__ Bh,
                         __nv_bfloat16* __restrict__ Bl) {
    int idx = blockIdx.x * blockDim.x + threadIdx.x;
    if (idx >= H * K) return;
    int c = idx / K, k = idx - c * K;
    __nv_bfloat16 h, l;
    split_bf16(W[(size_t)k * H + c], h, l);
    Bh[idx] = h;
    Bl[idx] = l;
}

// --------------------------- gather agg + fused split -----------------------

__global__ void k_agg1(int n) {
    int v = (blockIdx.x * blockDim.x + threadIdx.x) >> 5;
    if (v >= n) return;
    int lane = threadIdx.x & 31;
    float4 acc = ((const float4*)(g_p1 + (size_t)v * F1))[lane];
    int i = g_rowptr[v] + g_boff[v >> 10], end = i + g_cnt[v];
    for (; i + 1 < end; i += 2) {
        int u0 = g_eidx[i], u1 = g_eidx[i + 1];
        float4 m0 = ((const float4*)(g_p1 + (size_t)u0 * F1))[lane];
        float4 m1 = ((const float4*)(g_p1 + (size_t)u1 * F1))[lane];
        acc.x += m0.x + m1.x; acc.y += m0.y + m1.y;
        acc.z += m0.z + m1.z; acc.w += m0.w + m1.w;
    }
    if (i < end) {
        int u = g_eidx[i];
        float4 m = ((const float4*)(g_p1 + (size_t)u * F1))[lane];
        acc.x += m.x; acc.y += m.y; acc.z += m.z; acc.w += m.w;
    }
    float d = g_dinv[v];
    acc.x *= d; acc.y *= d; acc.z *= d; acc.w *= d;
    __nv_bfloat16 h0, l0, h1, l1, h2, l2, h3, l3;
    split_bf16(acc.x, h0, l0); split_bf16(acc.y, h1, l1);
    split_bf16(acc.z, h2, l2); split_bf16(acc.w, h3, l3);
    __nv_bfloat162* oh = (__nv_bfloat162*)(g_a1h + (size_t)v * F1);
    __nv_bfloat162* ol = (__nv_bfloat162*)(g_a1l + (size_t)v * F1);
    oh[lane * 2]     = __halves2bfloat162(h0, h1);
    oh[lane * 2 + 1] = __halves2bfloat162(h2, h3);
    ol[lane * 2]     = __halves2bfloat162(l0, l1);
    ol[lane * 2 + 1] = __halves2bfloat162(l2, l3);
}

__global__ void k_agg2(int n) {
    int v = (blockIdx.x * blockDim.x + threadIdx.x) >> 5;
    if (v >= n) return;
    int lane = threadIdx.x & 31;
    const float4* pr = (const float4*)(g_p2 + (size_t)v * H);
    float4 a0 = pr[lane];
    float4 a1 = pr[lane + 32];
    int i = g_rowptr[v] + g_boff[v >> 10], end = i + g_cnt[v];
    for (; i + 1 < end; i += 2) {
        int u0 = g_eidx[i], u1 = g_eidx[i + 1];
        const float4* r0 = (const float4*)(g_p2 + (size_t)u0 * H);
        const float4* r1 = (const float4*)(g_p2 + (size_t)u1 * H);
        float4 m00 = r0[lane], m01 = r0[lane + 32];
        float4 m10 = r1[lane], m11 = r1[lane + 32];
        a0.x += m00.x + m10.x; a0.y += m00.y + m10.y;
        a0.z += m00.z + m10.z; a0.w += m00.w + m10.w;
        a1.x += m01.x + m11.x; a1.y += m01.y + m11.y;
        a1.z += m01.z + m11.z; a1.w += m01.w + m11.w;
    }
    if (i < end) {
        int u = g_eidx[i];
        const float4* mr = (const float4*)(g_p2 + (size_t)u * H);
        float4 m0 = mr[lane], m1 = mr[lane + 32];
        a0.x += m0.x; a0.y += m0.y; a0.z += m0.z; a0.w += m0.w;
        a1.x += m1.x; a1.y += m1.y; a1.z += m1.z; a1.w += m1.w;
    }
    float d = g_dinv[v];
    a0.x *= d; a0.y *= d; a0.z *= d; a0.w *= d;
    a1.x *= d; a1.y *= d; a1.z *= d; a1.w *= d;
    __nv_bfloat162* oh = (__nv_bfloat162*)(g_a2h + (size_t)v * H);
    __nv_bfloat162* ol = (__nv_bfloat162*)(g_a2l + (size_t)v * H);
    __nv_bfloat16 h0, l0, h1, l1, h2, l2, h3, l3;
    split_bf16(a0.x, h0, l0); split_bf16(a0.y, h1, l1);
    split_bf16(a0.z, h2, l2); split_bf16(a0.w, h3, l3);
    oh[lane * 2]     = __halves2bfloat162(h0, h1);
    oh[lane * 2 + 1] = __halves2bfloat162(h2, h3);
    ol[lane * 2]     = __halves2bfloat162(l0, l1);
    ol[lane * 2 + 1] = __halves2bfloat162(l2, l3);
    split_bf16(a1.x, h0, l0); split_bf16(a1.y, h1, l1);
    split_bf16(a1.z, h2, l2); split_bf16(a1.w, h3, l3);
    oh[64 + lane * 2]     = __halves2bfloat162(h0, h1);
    oh[64 + lane * 2 + 1] = __halves2bfloat162(h2, h3);
    ol[64 + lane * 2]     = __halves2bfloat162(l0, l1);
    ol[64 + lane * 2 + 1] = __halves2bfloat162(l2, l3);
}

// ---------------------------------------------------------------------------
// mma.sync GEMM, full-width tiles: block 128(M) x 256(N), BK=32, 512 threads,
// 16 warps (4M x 4N), warp tile 32x64 (same proven inner loop as before).
// Smem [row][40 bf16] (80B stride, conflict-free ldmatrix).
// A buffers: 2 stages x hi/lo x 10240B @ 0;  B: 2 x hi/lo x 20480B @ 40960.
// EPI==1: p2 = d*relu(C+b1)
// EPI==2: out[r] = relu(C+b2) @ Wfc + bfc   (4-way warpN smem reduction)
// ---------------------------------------------------------------------------

#define A_TB   10240
#define B_TB   20480
#define B_BASE 40960
#define SMEM_GEMM (B_BASE + 4 * B_TB)   // 122880 bytes

__device__ __forceinline__ void mma_bf16(float* c, const uint32_t* a,
                                         uint32_t b0, uint32_t b1) {
    asm volatile(
        "mma.sync.aligned.m16n8k16.row.col.f32.bf16.bf16.f32 "
        "{%0,%1,%2,%3}, {%4,%5,%6,%7}, {%8,%9}, {%0,%1,%2,%3};\n"
        : "+f"(c[0]), "+f"(c[1]), "+f"(c[2]), "+f"(c[3])
        : "r"(a[0]), "r"(a[1]), "r"(a[2]), "r"(a[3]), "r"(b0), "r"(b1));
}

__device__ __forceinline__ void ldm_x4(uint32_t* r, uint32_t addr) {
    asm volatile(
        "ldmatrix.sync.aligned.m8n8.x4.shared.b16 {%0,%1,%2,%3}, [%4];\n"
        : "=r"(r[0]), "=r"(r[1]), "=r"(r[2]), "=r"(r[3]) : "r"(addr));
}

__device__ __forceinline__ void cpa16(uint32_t dst, const void* src) {
    asm volatile("cp.async.cg.shared.global [%0], [%1], 16;\n" :: "r"(dst), "l"(src));
}
__device__ __forceinline__ void cpa_commit() { asm volatile("cp.async.commit_group;\n"); }
template <int N>
__device__ __forceinline__ void cpa_wait() {
    asm volatile("cp.async.wait_group %0;\n" :: "n"(N));
}

template <int K, int EPI>
__global__ void __launch_bounds__(512)
k_gemm_tc(const __nv_bfloat16* __restrict__ Ah, const __nv_bfloat16* __restrict__ Al,
          const __nv_bfloat16* __restrict__ Bh, const __nv_bfloat16* __restrict__ Bl,
          const float* __restrict__ bias, const float* __restrict__ Wfc,
          const float* __restrict__ bfc, float* __restrict__ out, int M) {
    extern __shared__ __align__(16) char smem[];

    int tid = threadIdx.x, lane = tid & 31, warp = tid >> 5;
    int warpM = warp & 3, warpN = warp >> 2;           // 4 x 4
    int rowBase = blockIdx.x * 128;
    uint32_t sb = (uint32_t)__cvta_generic_to_shared(smem);

    float acc[2][8][4];
#pragma unroll
    for (int mf = 0; mf < 2; mf++)
#pragma unroll
        for (int nf = 0; nf < 8; nf++)
#pragma unroll
            for (int i = 0; i < 4; i++) acc[mf][nf][i] = 0.0f;

    auto load_stage = [&](int s, int k0) {
#pragma unroll
        for (int it = 0; it < 6; it++) {
            int id = tid + it * 512;                   // 0..3071
            if (id < 1024) {                           // A: 2 parts x 128r x 4c
                int p = id >> 9, rem = id & 511, r = rem >> 2, c = rem & 3;
                uint32_t dst = sb + (uint32_t)((s * 2 + p) * A_TB + r * 80 + c * 16);
                const __nv_bfloat16* src =
                    (p ? Al : Ah) + (size_t)(rowBase + r) * K + k0 + c * 8;
                cpa16(dst, src);
            } else {                                   // B: 2 parts x 256r x 4c
                int id2 = id - 1024;
                int p = id2 >> 10, rem = id2 & 1023, r = rem >> 2, c = rem & 3;
                uint32_t dst = sb + (uint32_t)(B_BASE + (s * 2 + p) * B_TB + r * 80 + c * 16);
                const __nv_bfloat16* src =
                    (p ? Bl : Bh) + (size_t)r * K + k0 + c * 8;
                cpa16(dst, src);
            }
        }
    };

    auto compute_stage = [&](int s) {
        uint32_t aBh = sb + (uint32_t)((s * 2 + 0) * A_TB);
        uint32_t aBl = sb + (uint32_t)((s * 2 + 1) * A_TB);
        uint32_t bBh = sb + (uint32_t)(B_BASE + (s * 2 + 0) * B_TB);
        uint32_t bBl = sb + (uint32_t)(B_BASE + (s * 2 + 1) * B_TB);
        uint32_t aoff = (uint32_t)(warpM * 32 + (lane & 15)) * 80 + (lane >> 4) * 16;
        uint32_t boff = (uint32_t)(warpN * 64 + ((lane >> 4) << 3) + (lane & 7)) * 80
                      + ((lane >> 3) & 1) * 16;
#pragma unroll
        for (int ks = 0; ks < 2; ks++) {
            uint32_t kb = ks * 32;
            uint32_t ah[2][4], al[2][4], bhf[4][4], blf[4][4];
#pragma unroll
            for (int mf = 0; mf < 2; mf++) {
                ldm_x4(ah[mf], aBh + aoff + mf * (16 * 80) + kb);
                ldm_x4(al[mf], aBl + aoff + mf * (16 * 80) + kb);
            }
#pragma unroll
            for (int nfp = 0; nfp < 4; nfp++) {
                ldm_x4(bhf[nfp], bBh + boff + nfp * (16 * 80) + kb);
                ldm_x4(blf[nfp], bBl + boff + nfp * (16 * 80) + kb);
            }
#pragma unroll
            for (int nf = 0; nf < 8; nf++) {
                uint32_t b0h = bhf[nf >> 1][(nf & 1) * 2], b1h = bhf[nf >> 1][(nf & 1) * 2 + 1];
                uint32_t b0l = blf[nf >> 1][(nf & 1) * 2], b1l = blf[nf >> 1][(nf & 1) * 2 + 1];
#pragma unroll
                for (int mf = 0; mf < 2; mf++) {
                    mma_bf16(acc[mf][nf], ah[mf], b0h, b1h);
                    mma_bf16(acc[mf][nf], ah[mf], b0l, b1l);
                    mma_bf16(acc[mf][nf], al[mf], b0h, b1h);
                }
            }
        }
    };

    const int T = K / 32;
    load_stage(0, 0);
    cpa_commit();
#pragma unroll 2
    for (int t = 0; t < T; t++) {
        if (t + 1 < T) {
            load_stage((t + 1) & 1, (t + 1) * 32);
            cpa_commit();
            cpa_wait<1>();
        } else {
            cpa_wait<0>();
        }
        __syncthreads();
        compute_stage(t & 1);
        __syncthreads();
    }

    // ---- epilogue
    if (EPI == 1) {
#pragma unroll
        for (int mf = 0; mf < 2; mf++)
#pragma unroll
            for (int rr = 0; rr < 2; rr++) {
                int r = rowBase + warpM * 32 + mf * 16 + (lane >> 2) + rr * 8;
                if (r >= M) continue;
                float d = g_dinv[r];
#pragma unroll
                for (int nf = 0; nf < 8; nf++) {
                    int c = warpN * 64 + nf * 8 + (lane & 3) * 2;
                    float v0 = fmaxf(acc[mf][nf][rr * 2 + 0] + bias[c], 0.f) * d;
                    float v1 = fmaxf(acc[mf][nf][rr * 2 + 1] + bias[c + 1], 0.f) * d;
                    *(float2*)&g_p2[(size_t)r * H + c] = make_float2(v0, v1);
                }
            }
    } else {
        float* sred = (float*)smem;                 // 128 rows x 4 warpN partials
#pragma unroll
        for (int mf = 0; mf < 2; mf++)
#pragma unroll
            for (int rr = 0; rr < 2; rr++) {
                float p = 0.0f;
#pragma unroll
                for (int nf = 0; nf < 8; nf++) {
                    int c = warpN * 64 + nf * 8 + (lane & 3) * 2;
                    p += fmaxf(acc[mf][nf][rr * 2 + 0] + bias[c], 0.f) * Wfc[c];
                    p += fmaxf(acc[mf][nf][rr * 2 + 1] + bias[c + 1], 0.f) * Wfc[c + 1];
                }
                p += __shfl_xor_sync(0xFFFFFFFFu, p, 1);
                p += __shfl_xor_sync(0xFFFFFFFFu, p, 2);
                if ((lane & 3) == 0) {
                    int rl = warpM * 32 + mf * 16 + (lane >> 2) + rr * 8;
                    sred[rl * 4 + warpN] = p;
                }
            }
        __syncthreads();
        if (tid < 128) {
            int r = rowBase + tid;
            if (r < M)
                out[r] = sred[tid * 4] + sred[tid * 4 + 1]
                       + sred[tid * 4 + 2] + sred[tid * 4 + 3] + bfc[0];
        }
    }
}

// ---------------------------------------------------------------------------

extern "C" void kernel_launch(void* const* d_in, const int* in_sizes, int n_in,
                              void* d_out, int out_size) {
    const float* x   = (const float*)d_in[0];
    const void*  ei  = d_in[1];
    const float* W1  = (const float*)d_in[2];
    const float* b1  = (const float*)d_in[3];
    const float* W2  = (const float*)d_in[4];
    const float* b2  = (const float*)d_in[5];
    const float* Wfc = (const float*)d_in[6];
    const float* bfc = (const float*)d_in[7];
    float*       out = (float*)d_out;

    int h   = in_sizes[3];            // 256
    int fin = in_sizes[2] / h;        // 128
    int n   = in_sizes[0] / fin;      // 50000
    int E   = in_sizes[1] / 2;        // 800000
    (void)h; (void)n_in; (void)out_size;

    int nb = (n + SCAN_B - 1) / SCAN_B;

    cudaFuncSetAttribute(k_gemm_tc<F1, 1>,
                         cudaFuncAttributeMaxDynamicSharedMemorySize, SMEM_GEMM);
    cudaFuncSetAttribute(k_gemm_tc<H, 2>,
                         cudaFuncAttributeMaxDynamicSharedMemorySize, SMEM_GEMM);

    __nv_bfloat16 *a1h, *a1l, *a2h, *a2l, *w1h, *w1l, *w2h, *w2l;
    cudaGetSymbolAddress((void**)&a1h, g_a1h);
    cudaGetSymbolAddress((void**)&a1l, g_a1l);
    cudaGetSymbolAddress((void**)&a2h, g_a2h);
    cudaGetSymbolAddress((void**)&a2l, g_a2l);
    cudaGetSymbolAddress((void**)&w1h, g_w1h);
    cudaGetSymbolAddress((void**)&w1l, g_w1l);
    cudaGetSymbolAddress((void**)&w2h, g_w2h);
    cudaGetSymbolAddress((void**)&w2l, g_w2l);

    k_detect_init<<<(n + 255) / 256, 256>>>((const int*)ei, n);
    k_extract<<<(2 * E + 255) / 256, 256>>>(ei, E, n);

    k_scan_block<<<nb, SCAN_B>>>(n);
    k_scan_sums<<<1, 64>>>(nb);
    k_fill   <<<(E + 255) / 256, 256>>>(E);

    k_splitW<F1><<<(H * F1 + 255) / 256, 256>>>(W1, w1h, w1l);
    k_splitW<H> <<<(H * H  + 255) / 256, 256>>>(W2, w2h, w2l);

    k_prep<<<(n * 32 + 255) / 256, 256>>>(x, n);
    k_agg1<<<(n * 32 + 255) / 256, 256>>>(n);

    int gblocks = (n + 127) / 128;
    k_gemm_tc<F1, 1><<<gblocks, 512, SMEM_GEMM>>>(a1h, a1l, w1h, w1l, b1, nullptr, nullptr, nullptr, n);
    k_agg2<<<(n * 32 + 255) / 256, 256>>>(n);
    k_gemm_tc<H, 2><<<gblocks, 512, SMEM_GEMM>>>(a2h, a2l, w2h, w2l, b2, Wfc, bfc, out, n);
}